// round 4
// baseline (speedup 1.0000x reference)
#include <cuda_runtime.h>
#include <cstdint>

// B=1024, T=200, IN=H=128. Rows = B*T = 204800.
__device__ float g_xall[(size_t)204800 * 384];
__device__ float g_logits[204800];
__device__ float g_att[204800];
__device__ float g_hfinal[1024 * 128];

// ---------------- K1: logits + x-projections ----------------
// block: 256 thr, 64 rows. smem: wsm[128][132], tsm[64][132], hsm[64][132], lg[128]
__global__ void k1_ff(const float* __restrict__ targets, const float* __restrict__ hist,
                      const float* __restrict__ Ww,  const float* __restrict__ Wb,
                      const float* __restrict__ xuw, const float* __restrict__ xub,
                      const float* __restrict__ xrw, const float* __restrict__ xrb,
                      const float* __restrict__ xgw, const float* __restrict__ xgb)
{
    extern __shared__ float sm[];
    float* wsm = sm;                 // 128*132 = 16896
    float* tsm = wsm + 16896;        // 64*132  = 8448
    float* hsm = tsm + 8448;         // 8448
    float* lg  = hsm + 8448;         // 128
    const int t = threadIdx.x;
    const size_t row0 = (size_t)blockIdx.x * 64;

    for (int i = t; i < 64 * 128; i += 256) {
        int r = i >> 7, c = i & 127;
        tsm[r * 132 + c] = targets[(row0 + r) * 128 + c];
        hsm[r * 132 + c] = hist[(row0 + r) * 128 + c];
    }
    if (t < 128) lg[t] = 0.f;

    const float* Wm[4] = {Ww, xuw, xrw, xgw};
    const float* Bm[4] = {Wb, xub, xrb, xgb};
    const int co = t & 63, ro = t >> 6;   // ro 0..3 -> rows ro*16..+15
    const int c0 = co * 2;
    const int wrp = t >> 5;

    for (int m = 0; m < 4; m++) {
        __syncthreads();   // previous compute / smem fills done
        const float* W = Wm[m];
        for (int i = t; i < 16384; i += 256) {
            int o = i >> 7, k = i & 127;
            wsm[k * 132 + o] = W[i];
        }
        __syncthreads();
        float2 bw = *(const float2*)(Bm[m] + c0);
        float2 acc[16];
        if (m == 0) {
            #pragma unroll
            for (int i = 0; i < 16; i++) acc[i] = bw;
        } else {
            #pragma unroll
            for (int i = 0; i < 16; i++) acc[i] = make_float2(0.f, 0.f);
        }
        const float* xb = (m == 0) ? tsm : hsm;
        #pragma unroll 2
        for (int k = 0; k < 128; k += 2) {
            float2 w0 = *(const float2*)(wsm + k * 132 + c0);
            float2 w1 = *(const float2*)(wsm + (k + 1) * 132 + c0);
            #pragma unroll
            for (int i = 0; i < 16; i++) {
                float2 xv = *(const float2*)(xb + (ro * 16 + i) * 132 + k);
                acc[i].x += w0.x * xv.x; acc[i].y += w0.y * xv.x;
                acc[i].x += w1.x * xv.y; acc[i].y += w1.y * xv.y;
            }
        }
        if (m == 0) {
            // logit = sum_o aw[o]*hist[o]; reduce 64 cols across 2 warps, no atomics
            #pragma unroll
            for (int i = 0; i < 16; i++) {
                int r = ro * 16 + i;
                float p = acc[i].x * hsm[r * 132 + c0] + acc[i].y * hsm[r * 132 + c0 + 1];
                #pragma unroll
                for (int off = 16; off; off >>= 1) p += __shfl_down_sync(0xffffffffu, p, off);
                if ((t & 31) == 0) lg[r * 2 + (wrp & 1)] = p;
            }
        } else {
            #pragma unroll
            for (int i = 0; i < 16; i++) {
                int r = ro * 16 + i;
                float2 v = make_float2(acc[i].x + bw.x, acc[i].y + bw.y);
                *(float2*)(g_xall + (row0 + r) * 384 + (size_t)(m - 1) * 128 + c0) = v;
            }
        }
    }
    __syncthreads();
    if (t < 64) g_logits[row0 + t] = lg[t * 2] + lg[t * 2 + 1];
}

// ---------------- K2: softmax over T per batch ----------------
__global__ void k2_softmax()
{
    __shared__ float red[256];
    const int b = blockIdx.x, t = threadIdx.x;
    float v = (t < 200) ? g_logits[b * 200 + t] : -1e30f;
    red[t] = v; __syncthreads();
    for (int s = 128; s; s >>= 1) { if (t < s) red[t] = fmaxf(red[t], red[t + s]); __syncthreads(); }
    float mx = red[0]; __syncthreads();
    float e = (t < 200) ? __expf(v - mx) : 0.f;
    red[t] = e; __syncthreads();
    for (int s = 128; s; s >>= 1) { if (t < s) red[t] += red[t + s]; __syncthreads(); }
    float inv = __fdividef(1.f, red[0]);
    if (t < 200) g_att[b * 200 + t] = e * inv;
}

// ---------------- K3: sequential GRU-style scan ----------------
// 128 blocks x 256 thr; block owns 8 batch rows for all 200 steps.
// smem: wu/wr/wg [128][132] each, hsm[8][132]
__global__ void k3_scan(const float* __restrict__ huw, const float* __restrict__ hub,
                        const float* __restrict__ hrw, const float* __restrict__ hrb,
                        const float* __restrict__ hgw, const float* __restrict__ hgb)
{
    extern __shared__ float sm[];
    float* wu = sm;
    float* wr = wu + 16896;
    float* wg = wr + 16896;
    float* hsm = wg + 16896;   // 8*132 = 1056
    const int t = threadIdx.x;
    for (int i = t; i < 16384; i += 256) {
        int o = i >> 7, k = i & 127;
        wu[k * 132 + o] = huw[i];
        wr[k * 132 + o] = hrw[i];
        wg[k * 132 + o] = hgw[i];
    }
    for (int i = t; i < 8 * 132; i += 256) hsm[i] = 0.f;
    const int o = t & 127, rh = t >> 7;           // rh 0/1 -> rows rh*4..+3
    const float bu = hub[o], br = hrb[o], bg = hgb[o];
    const size_t rowb = (size_t)blockIdx.x * 8;
    __syncthreads();

    for (int step = 0; step < 200; step++) {
        float xu[4], xr[4], xg[4], at[4];
        #pragma unroll
        for (int i = 0; i < 4; i++) {
            size_t brow = rowb + rh * 4 + i;
            size_t idx = (brow * 200 + step) * 384;
            xu[i] = g_xall[idx + o];
            xr[i] = g_xall[idx + 128 + o];
            xg[i] = g_xall[idx + 256 + o];
            at[i] = g_att[brow * 200 + step];
        }
        float su[4] = {0,0,0,0}, sr[4] = {0,0,0,0}, sg[4] = {0,0,0,0};
        #pragma unroll 2
        for (int k = 0; k < 128; k += 2) {
            float u0 = wu[k * 132 + o], u1 = wu[(k + 1) * 132 + o];
            float r0 = wr[k * 132 + o], r1 = wr[(k + 1) * 132 + o];
            float g0 = wg[k * 132 + o], g1 = wg[(k + 1) * 132 + o];
            #pragma unroll
            for (int i = 0; i < 4; i++) {
                float2 hv = *(const float2*)(hsm + (rh * 4 + i) * 132 + k);
                su[i] += u0 * hv.x + u1 * hv.y;
                sr[i] += r0 * hv.x + r1 * hv.y;
                sg[i] += g0 * hv.x + g1 * hv.y;
            }
        }
        float hn[4];
        #pragma unroll
        for (int i = 0; i < 4; i++) {
            float hold = hsm[(rh * 4 + i) * 132 + o];
            float uu = __fdividef(1.f, 1.f + __expf(-(su[i] + bu + xu[i]))) * at[i];
            float rr = __fdividef(1.f, 1.f + __expf(-(sr[i] + br + xr[i])));
            float pre = xg[i] + rr * (sg[i] + bg);
            float gg = 1.f - __fdividef(2.f, __expf(2.f * pre) + 1.f);
            hn[i] = (1.f - uu) * hold + uu * gg;
        }
        __syncthreads();
        #pragma unroll
        for (int i = 0; i < 4; i++) hsm[(rh * 4 + i) * 132 + o] = hn[i];
        __syncthreads();
    }
    #pragma unroll
    for (int i = 0; i < 4; i++)
        g_hfinal[(rowb + rh * 4 + i) * 128 + o] = hsm[(rh * 4 + i) * 132 + o];
}

// ---------------- K4: final linear [h, targets[:,0]] @ ln2_w^T + b ----------------
__global__ void k4_out(const float* __restrict__ targets, const float* __restrict__ w,
                       const float* __restrict__ bias, float* __restrict__ out)
{
    __shared__ __align__(16) float insm[256];
    const int b = blockIdx.x, t = threadIdx.x;   // 128 threads
    insm[t] = g_hfinal[b * 128 + t];
    insm[128 + t] = targets[(size_t)b * 200 * 128 + t];
    __syncthreads();
    float acc = bias[t];
    const float4* wr4 = (const float4*)(w + (size_t)t * 256);
    #pragma unroll 8
    for (int k = 0; k < 64; k++) {
        float4 wv = wr4[k];
        float4 xv = *(const float4*)(insm + k * 4);
        acc += wv.x * xv.x + wv.y * xv.y + wv.z * xv.z + wv.w * xv.w;
    }
    out[b * 128 + t] = acc;
}

extern "C" void kernel_launch(void* const* d_in, const int* in_sizes, int n_in,
                              void* d_out, int out_size)
{
    const float* targets = (const float*)d_in[0];
    const float* hist    = (const float*)d_in[1];
    const float* Ww  = (const float*)d_in[2];  const float* Wb  = (const float*)d_in[3];
    const float* xuw = (const float*)d_in[4];  const float* xub = (const float*)d_in[5];
    const float* huw = (const float*)d_in[6];  const float* hub = (const float*)d_in[7];
    const float* xrw = (const float*)d_in[8];  const float* xrb = (const float*)d_in[9];
    const float* hrw = (const float*)d_in[10]; const float* hrb = (const float*)d_in[11];
    const float* xgw = (const float*)d_in[12]; const float* xgb = (const float*)d_in[13];
    const float* hgw = (const float*)d_in[14]; const float* hgb = (const float*)d_in[15];
    const float* lnw = (const float*)d_in[16]; const float* lnb = (const float*)d_in[17];
    float* out = (float*)d_out;

    const int smem1 = (16896 + 8448 + 8448 + 128) * 4;        // 135,680
    const int smem3 = (16896 * 3 + 1056) * 4;                 // 206,976
    cudaFuncSetAttribute(k1_ff,   cudaFuncAttributeMaxDynamicSharedMemorySize, smem1);
    cudaFuncSetAttribute(k3_scan, cudaFuncAttributeMaxDynamicSharedMemorySize, smem3);

    k1_ff<<<3200, 256, smem1>>>(targets, hist, Ww, Wb, xuw, xub, xrw, xrb, xgw, xgb);
    k2_softmax<<<1024, 256>>>();
    k3_scan<<<128, 256, smem3>>>(huw, hub, hrw, hrb, hgw, hgb);
    k4_out<<<1024, 128>>>(targets, lnw, lnb, out);
}

// round 5
// speedup vs baseline: 2.7740x; 2.7740x over previous
#include <cuda_runtime.h>
#include <cuda_fp16.h>
#include <cstdint>

// B=1024, T=200, IN=H=128. rows = 204800.
__device__ __half g_xall16[(size_t)204800 * 384];   // xu|xr|xg fp16, biases folded (xg bias folded too; see note)
__device__ float g_logits[204800];
__device__ float g_att[204800];
__device__ float g_hfinal[1024 * 128];

__device__ __forceinline__ uint32_t smem_u32(const void* p) {
    return (uint32_t)__cvta_generic_to_shared(p);
}
__device__ __forceinline__ void ldmatrix_x4(uint32_t a[4], uint32_t addr) {
    asm volatile("ldmatrix.sync.aligned.m8n8.x4.shared.b16 {%0,%1,%2,%3}, [%4];"
                 : "=r"(a[0]), "=r"(a[1]), "=r"(a[2]), "=r"(a[3]) : "r"(addr));
}
__device__ __forceinline__ void mma16816(float c[4], const uint32_t a[4], const uint32_t b[2]) {
    asm volatile("mma.sync.aligned.m16n8k16.row.col.f32.f16.f16.f32 "
                 "{%0,%1,%2,%3},{%4,%5,%6,%7},{%8,%9},{%0,%1,%2,%3};"
                 : "+f"(c[0]), "+f"(c[1]), "+f"(c[2]), "+f"(c[3])
                 : "r"(a[0]), "r"(a[1]), "r"(a[2]), "r"(a[3]), "r"(b[0]), "r"(b[1]));
}
__device__ __forceinline__ uint32_t f2h2(float x, float y) {
    __half2 h = __floats2half2_rn(x, y);
    return *reinterpret_cast<uint32_t*>(&h);
}

// ================= K1: logits + x projections (tensor core) =================
// grid 3200, block 256 (8 warps). 64 rows/CTA.
// smem: tgt16[64][136] (17408B) | hst16[64][136] (17408B) | hst32[64][132] (33792B) | lgp[2][64] (512B)
__global__ __launch_bounds__(256) void k1_ff(
    const float* __restrict__ targets, const float* __restrict__ hist,
    const float* __restrict__ Ww,  const float* __restrict__ Wb,
    const float* __restrict__ xuw, const float* __restrict__ xub,
    const float* __restrict__ xrw, const float* __restrict__ xrb,
    const float* __restrict__ xgw, const float* __restrict__ xgb)
{
    extern __shared__ char sm[];
    __half* tgt16 = (__half*)sm;
    __half* hst16 = (__half*)(sm + 17408);
    float*  hst32 = (float*)(sm + 34816);
    float*  lgp   = (float*)(sm + 68608);
    const int t = threadIdx.x;
    const size_t row0 = (size_t)blockIdx.x * 64;

    for (int i = t; i < 64 * 128; i += 256) {
        int r = i >> 7, c = i & 127;
        float tv = targets[(row0 + r) * 128 + c];
        float hv = hist[(row0 + r) * 128 + c];
        tgt16[r * 136 + c] = __float2half_rn(tv);
        hst16[r * 136 + c] = __float2half_rn(hv);
        hst32[r * 132 + c] = hv;
    }
    __syncthreads();

    const int w = t >> 5, lane = t & 31;
    const int mt = w & 3, nh = w >> 2;       // m-tile (rows mt*16..), col-half nh
    const int q = lane & 3, l4 = lane >> 2;
    const int r0 = mt * 16 + l4, r1 = r0 + 8;

    uint32_t afr[8][4];
    // ---------- phase A: aw = tgt @ Ww^T, fused logit row-dot ----------
    {
        uint32_t base = smem_u32(tgt16) + (mt * 16 + (lane & 15)) * 272 + (lane >> 4) * 16;
        #pragma unroll
        for (int kt = 0; kt < 8; kt++) ldmatrix_x4(afr[kt], base + kt * 32);
    }
    float p0 = 0.f, p1 = 0.f;
    #pragma unroll
    for (int nt = 0; nt < 8; nt++) {
        const int c0 = nh * 64 + nt * 8;
        float c[4] = {0.f, 0.f, 0.f, 0.f};
        const int n = c0 + l4;
        #pragma unroll
        for (int kt = 0; kt < 8; kt++) {
            float2 wa = *(const float2*)&Ww[n * 128 + kt * 16 + 2 * q];
            float2 wb = *(const float2*)&Ww[n * 128 + kt * 16 + 2 * q + 8];
            uint32_t b[2] = {f2h2(wa.x, wa.y), f2h2(wb.x, wb.y)};
            mma16816(c, afr[kt], b);
        }
        float2 wb2 = *(const float2*)&Wb[c0 + 2 * q];
        float2 h0 = *(const float2*)&hst32[r0 * 132 + c0 + 2 * q];
        float2 h1 = *(const float2*)&hst32[r1 * 132 + c0 + 2 * q];
        p0 += (c[0] + wb2.x) * h0.x + (c[1] + wb2.y) * h0.y;
        p1 += (c[2] + wb2.x) * h1.x + (c[3] + wb2.y) * h1.y;
    }
    p0 += __shfl_xor_sync(~0u, p0, 1); p0 += __shfl_xor_sync(~0u, p0, 2);
    p1 += __shfl_xor_sync(~0u, p1, 1); p1 += __shfl_xor_sync(~0u, p1, 2);
    if (q == 0) {
        lgp[nh * 64 + mt * 16 + l4] = p0;
        lgp[nh * 64 + mt * 16 + l4 + 8] = p1;
    }

    // ---------- phase B: xu/xr/xg = hist @ W^T + b, store fp16 ----------
    {
        uint32_t base = smem_u32(hst16) + (mt * 16 + (lane & 15)) * 272 + (lane >> 4) * 16;
        #pragma unroll
        for (int kt = 0; kt < 8; kt++) ldmatrix_x4(afr[kt], base + kt * 32);
    }
    #pragma unroll
    for (int nt = 0; nt < 24; nt++) {
        const int gc = nh * 192 + nt * 8;
        const int m = gc >> 7, cc = gc & 127;
        const float* W  = (m == 0) ? xuw : (m == 1) ? xrw : xgw;
        const float* Bv = (m == 0) ? xub : (m == 1) ? xrb : xgb;
        float2 bb = *(const float2*)&Bv[cc + 2 * q];
        float c[4] = {bb.x, bb.y, bb.x, bb.y};
        const int n = cc + l4;
        #pragma unroll
        for (int kt = 0; kt < 8; kt++) {
            float2 wa = *(const float2*)&W[n * 128 + kt * 16 + 2 * q];
            float2 wb = *(const float2*)&W[n * 128 + kt * 16 + 2 * q + 8];
            uint32_t b[2] = {f2h2(wa.x, wa.y), f2h2(wb.x, wb.y)};
            mma16816(c, afr[kt], b);
        }
        size_t g0 = (row0 + r0) * 384 + gc + 2 * q;
        *(uint32_t*)&g_xall16[g0]             = f2h2(c[0], c[1]);
        *(uint32_t*)&g_xall16[g0 + 8 * 384]   = f2h2(c[2], c[3]);
    }
    __syncthreads();
    if (t < 64) g_logits[row0 + t] = lgp[t] + lgp[64 + t];
}

// NOTE: g_xall16 gate-2 slot holds xg INCLUDING xg_b (folded in k1);
// reference applies xg AFTER r*(...), which k3 respects (xg kept out of mma acc).

// ================= K2: softmax over T =================
__global__ void k2_softmax()
{
    __shared__ float red[256];
    const int b = blockIdx.x, t = threadIdx.x;
    float v = (t < 200) ? g_logits[b * 200 + t] : -1e30f;
    red[t] = v; __syncthreads();
    for (int s = 128; s; s >>= 1) { if (t < s) red[t] = fmaxf(red[t], red[t + s]); __syncthreads(); }
    float mx = red[0]; __syncthreads();
    float e = (t < 200) ? __expf(v - mx) : 0.f;
    red[t] = e; __syncthreads();
    for (int s = 128; s; s >>= 1) { if (t < s) red[t] += red[t + s]; __syncthreads(); }
    float inv = __fdividef(1.f, red[0]);
    if (t < 200) g_att[b * 200 + t] = e * inv;
}

// ================= K3: GRU scan, weights in register B-fragments =================
// grid 64, block 256 (8 warps). CTA owns 16 batch rows; warp w owns h-cols [16w,16w+16) x 3 gates.
__global__ __launch_bounds__(256) void k3_scan(
    const float* __restrict__ huw, const float* __restrict__ hub,
    const float* __restrict__ hrw, const float* __restrict__ hrb,
    const float* __restrict__ hgw, const float* __restrict__ hgb)
{
    __shared__ __align__(16) __half hsm[16 * 136];
    const int t = threadIdx.x, w = t >> 5, lane = t & 31;
    const int q = lane & 3, l4 = lane >> 2;
    const size_t rowb = (size_t)blockIdx.x * 16;
    const size_t br0 = rowb + l4, br1 = rowb + l4 + 8;

    // weight fragments: j = gate*2 + half
    uint32_t bfr[6][8][2];
    float2 bias2[6];
    #pragma unroll
    for (int j = 0; j < 6; j++) {
        const int g = j >> 1, hf = j & 1;
        const float* W  = (g == 0) ? huw : (g == 1) ? hrw : hgw;
        const float* Bv = (g == 0) ? hub : (g == 1) ? hrb : hgb;
        const int n = 16 * w + 8 * hf + l4;
        bias2[j] = *(const float2*)&Bv[16 * w + 8 * hf + 2 * q];
        #pragma unroll
        for (int kt = 0; kt < 8; kt++) {
            float2 wa = *(const float2*)&W[n * 128 + kt * 16 + 2 * q];
            float2 wb = *(const float2*)&W[n * 128 + kt * 16 + 2 * q + 8];
            bfr[j][kt][0] = f2h2(wa.x, wa.y);
            bfr[j][kt][1] = f2h2(wb.x, wb.y);
        }
    }
    for (int i = t; i < 16 * 136; i += 256) hsm[i] = __float2half(0.f);

    float hm[2][4] = {{0.f,0.f,0.f,0.f},{0.f,0.f,0.f,0.f}};
    uint32_t xp[6][2]; float at[2];
    // prefetch step 0
    #pragma unroll
    for (int j = 0; j < 6; j++) {
        const int g = j >> 1, hf = j & 1;
        const size_t col = (size_t)g * 128 + 16 * w + 8 * hf + 2 * q;
        xp[j][0] = *(const uint32_t*)&g_xall16[(br0 * 200) * 384 + col];
        xp[j][1] = *(const uint32_t*)&g_xall16[(br1 * 200) * 384 + col];
    }
    at[0] = g_att[br0 * 200]; at[1] = g_att[br1 * 200];
    __syncthreads();

    const uint32_t hbase = smem_u32(hsm) + (lane & 15) * 272 + (lane >> 4) * 16;

    for (int step = 0; step < 200; step++) {
        float acc[6][4];
        #pragma unroll
        for (int j = 0; j < 4; j++) {          // u, r gates: x folded into acc
            float2 x0 = __half22float2(*(__half2*)&xp[j][0]);
            float2 x1 = __half22float2(*(__half2*)&xp[j][1]);
            acc[j][0] = x0.x; acc[j][1] = x0.y; acc[j][2] = x1.x; acc[j][3] = x1.y;
        }
        float xg2[2][4];
        #pragma unroll
        for (int hf = 0; hf < 2; hf++) {       // g gate: x applied after r*(...)
            float2 x0 = __half22float2(*(__half2*)&xp[4 + hf][0]);
            float2 x1 = __half22float2(*(__half2*)&xp[4 + hf][1]);
            xg2[hf][0] = x0.x; xg2[hf][1] = x0.y; xg2[hf][2] = x1.x; xg2[hf][3] = x1.y;
            acc[4 + hf][0] = acc[4 + hf][1] = acc[4 + hf][2] = acc[4 + hf][3] = 0.f;
        }
        const float a0 = at[0], a1 = at[1];
        if (step < 199) {                      // prefetch next step off the critical path
            const int s1 = step + 1;
            #pragma unroll
            for (int j = 0; j < 6; j++) {
                const int g = j >> 1, hf = j & 1;
                const size_t col = (size_t)g * 128 + 16 * w + 8 * hf + 2 * q;
                xp[j][0] = *(const uint32_t*)&g_xall16[(br0 * 200 + s1) * 384 + col];
                xp[j][1] = *(const uint32_t*)&g_xall16[(br1 * 200 + s1) * 384 + col];
            }
            at[0] = g_att[br0 * 200 + s1]; at[1] = g_att[br1 * 200 + s1];
        }
        #pragma unroll
        for (int kt = 0; kt < 8; kt++) {
            uint32_t afr[4];
            ldmatrix_x4(afr, hbase + kt * 32);
            #pragma unroll
            for (int j = 0; j < 6; j++) mma16816(acc[j], afr, bfr[j][kt]);
        }
        float hn[2][4];
        #pragma unroll
        for (int hf = 0; hf < 2; hf++) {
            #pragma unroll
            for (int e = 0; e < 4; e++) {
                const float bU = (e & 1) ? bias2[hf].y     : bias2[hf].x;
                const float bR = (e & 1) ? bias2[2 + hf].y : bias2[2 + hf].x;
                const float bG = (e & 1) ? bias2[4 + hf].y : bias2[4 + hf].x;
                const float ae = (e < 2) ? a0 : a1;
                float u = __fdividef(1.f, 1.f + __expf(-(acc[hf][e] + bU))) * ae;
                float r = __fdividef(1.f, 1.f + __expf(-(acc[2 + hf][e] + bR)));
                float pre = xg2[hf][e] + r * (acc[4 + hf][e] + bG);
                float gg = 1.f - __fdividef(2.f, __expf(2.f * pre) + 1.f);
                hn[hf][e] = hm[hf][e] + u * (gg - hm[hf][e]);
            }
        }
        __syncthreads();
        #pragma unroll
        for (int hf = 0; hf < 2; hf++) {
            const int cc = 16 * w + 8 * hf + 2 * q;
            *(uint32_t*)((char*)hsm + l4 * 272 + cc * 2)       = f2h2(hn[hf][0], hn[hf][1]);
            *(uint32_t*)((char*)hsm + (l4 + 8) * 272 + cc * 2) = f2h2(hn[hf][2], hn[hf][3]);
            hm[hf][0] = hn[hf][0]; hm[hf][1] = hn[hf][1];
            hm[hf][2] = hn[hf][2]; hm[hf][3] = hn[hf][3];
        }
        __syncthreads();
    }
    #pragma unroll
    for (int hf = 0; hf < 2; hf++) {
        const int cc = 16 * w + 8 * hf + 2 * q;
        *(float2*)&g_hfinal[br0 * 128 + cc] = make_float2(hm[hf][0], hm[hf][1]);
        *(float2*)&g_hfinal[br1 * 128 + cc] = make_float2(hm[hf][2], hm[hf][3]);
    }
}

// ================= K4: final linear, 8 batches per block =================
__global__ __launch_bounds__(256) void k4_out(const float* __restrict__ targets,
                                              const float* __restrict__ w,
                                              const float* __restrict__ bias,
                                              float* __restrict__ out)
{
    __shared__ __align__(16) float xs[8][260];
    const int t = threadIdx.x;
    const int b0 = blockIdx.x * 8;
    for (int i = t; i < 8 * 128; i += 256) {
        int bb = i >> 7, c = i & 127;
        xs[bb][c]       = g_hfinal[(b0 + bb) * 128 + c];
        xs[bb][128 + c] = targets[(size_t)(b0 + bb) * 200 * 128 + c];
    }
    __syncthreads();
    const int col = t & 127, grp = t >> 7;    // grp 0/1 -> batches grp*4..+3
    float acc[4];
    const float bv = bias[col];
    #pragma unroll
    for (int i = 0; i < 4; i++) acc[i] = bv;
    const float4* wr = (const float4*)(w + (size_t)col * 256);
    #pragma unroll 4
    for (int k = 0; k < 64; k++) {
        float4 wv = wr[k];
        #pragma unroll
        for (int i = 0; i < 4; i++) {
            float4 xv = *(const float4*)&xs[grp * 4 + i][k * 4];
            acc[i] += wv.x * xv.x + wv.y * xv.y + wv.z * xv.z + wv.w * xv.w;
        }
    }
    #pragma unroll
    for (int i = 0; i < 4; i++)
        out[(b0 + grp * 4 + i) * 128 + col] = acc[i];
}

extern "C" void kernel_launch(void* const* d_in, const int* in_sizes, int n_in,
                              void* d_out, int out_size)
{
    const float* targets = (const float*)d_in[0];
    const float* hist    = (const float*)d_in[1];
    const float* Ww  = (const float*)d_in[2];  const float* Wb  = (const float*)d_in[3];
    const float* xuw = (const float*)d_in[4];  const float* xub = (const float*)d_in[5];
    const float* huw = (const float*)d_in[6];  const float* hub = (const float*)d_in[7];
    const float* xrw = (const float*)d_in[8];  const float* xrb = (const float*)d_in[9];
    const float* hrw = (const float*)d_in[10]; const float* hrb = (const float*)d_in[11];
    const float* xgw = (const float*)d_in[12]; const float* xgb = (const float*)d_in[13];
    const float* hgw = (const float*)d_in[14]; const float* hgb = (const float*)d_in[15];
    const float* lnw = (const float*)d_in[16]; const float* lnb = (const float*)d_in[17];
    float* out = (float*)d_out;

    const int smem1 = 69120;
    cudaFuncSetAttribute(k1_ff, cudaFuncAttributeMaxDynamicSharedMemorySize, smem1);

    k1_ff<<<3200, 256, smem1>>>(targets, hist, Ww, Wb, xuw, xub, xrw, xrb, xgw, xgb);
    k2_softmax<<<1024, 256>>>();
    k3_scan<<<64, 256>>>(huw, hub, hrw, hrb, hgw, hgb);
    k4_out<<<128, 256>>>(targets, lnw, lnb, out);
}

// round 6
// speedup vs baseline: 4.9577x; 1.7872x over previous
#include <cuda_runtime.h>
#include <cuda_fp16.h>
#include <cstdint>

// B=1024, T=200, IN=H=128. rows = 204800.
__device__ __half g_xall16[(size_t)204800 * 384];   // xu|xr|xg fp16 (biases folded in k1)
__device__ float g_logits[204800];
__device__ float g_att[204800];
__device__ float g_hfinal[1024 * 128];

__device__ __forceinline__ uint32_t smem_u32(const void* p) {
    return (uint32_t)__cvta_generic_to_shared(p);
}
__device__ __forceinline__ void ldmatrix_x4(uint32_t a[4], uint32_t addr) {
    asm volatile("ldmatrix.sync.aligned.m8n8.x4.shared.b16 {%0,%1,%2,%3}, [%4];"
                 : "=r"(a[0]), "=r"(a[1]), "=r"(a[2]), "=r"(a[3]) : "r"(addr));
}
__device__ __forceinline__ void mma16816(float c[4], const uint32_t a[4], uint32_t b0, uint32_t b1) {
    asm volatile("mma.sync.aligned.m16n8k16.row.col.f32.f16.f16.f32 "
                 "{%0,%1,%2,%3},{%4,%5,%6,%7},{%8,%9},{%0,%1,%2,%3};"
                 : "+f"(c[0]), "+f"(c[1]), "+f"(c[2]), "+f"(c[3])
                 : "r"(a[0]), "r"(a[1]), "r"(a[2]), "r"(a[3]), "r"(b0), "r"(b1));
}
__device__ __forceinline__ uint32_t f2h2(float x, float y) {
    __half2 h = __floats2half2_rn(x, y);
    return *reinterpret_cast<uint32_t*>(&h);
}
__device__ __forceinline__ float tanhapx(float x) {
    float y; asm("tanh.approx.f32 %0, %1;" : "=f"(y) : "f"(x)); return y;
}

// ================= K1: logits + x projections =================
// grid 400, block 256 (8 warps). Each CTA: stage 4 weight matrices fp16 in smem once,
// then 8 tiles of 64 rows. smem layout (bytes):
//   [0, 139264)        wsm16: 4 x [128 n][136 half] (272B row stride)
//   [139264, 156672)   tgt16: 64 x 136 half
//   [156672, 174080)   hst16: 64 x 136 half
//   [174080, 174592)   lgp:   128 float
#define K1_WSM_MAT (128 * 136)          // halves per matrix
#define K1_TGT_OFF 139264
#define K1_HST_OFF 156672
#define K1_LGP_OFF 174080
#define K1_SMEM    174592

__global__ __launch_bounds__(256) void k1_ff(
    const float* __restrict__ targets, const float* __restrict__ hist,
    const float* __restrict__ Ww,  const float* __restrict__ Wb,
    const float* __restrict__ xuw, const float* __restrict__ xub,
    const float* __restrict__ xrw, const float* __restrict__ xrb,
    const float* __restrict__ xgw, const float* __restrict__ xgb)
{
    extern __shared__ char sm[];
    __half* wsm16 = (__half*)sm;
    __half* tgt16 = (__half*)(sm + K1_TGT_OFF);
    __half* hst16 = (__half*)(sm + K1_HST_OFF);
    float*  lgp   = (float*)(sm + K1_LGP_OFF);
    const int t = threadIdx.x;

    // ---- stage weights fp16 once ----
    {
        const float* Wm[4] = {Ww, xuw, xrw, xgw};
        #pragma unroll
        for (int m = 0; m < 4; m++) {
            const float* W = Wm[m];
            __half* dst = wsm16 + m * K1_WSM_MAT;
            for (int i = t; i < 8192; i += 256) {           // float2 granules
                int r = i >> 6, c2 = i & 63;
                float2 v = *(const float2*)&W[r * 128 + c2 * 2];
                *(__half2*)&dst[r * 136 + c2 * 2] = __floats2half2_rn(v.x, v.y);
            }
        }
    }

    const int w = t >> 5, lane = t & 31;
    const int mt = w & 3, nh = w >> 2;
    const int q = lane & 3, l4 = lane >> 2;
    const int r0 = mt * 16 + l4, r1 = r0 + 8;
    const uint32_t wbase = smem_u32(wsm16) + ((lane & 7) * 272 + (lane >> 3) * 16);
    const uint32_t abase_t = smem_u32(tgt16) + (mt * 16 + (lane & 15)) * 272 + (lane >> 4) * 16;
    const uint32_t abase_h = smem_u32(hst16) + (mt * 16 + (lane & 15)) * 272 + (lane >> 4) * 16;

    for (int it = 0; it < 8; it++) {
        const size_t row0 = ((size_t)blockIdx.x * 8 + it) * 64;
        __syncthreads();   // previous tile fully consumed
        for (int i = t; i < 64 * 64; i += 256) {             // float2 granules
            int r = i >> 6, c2 = i & 63;
            float2 tv = *(const float2*)&targets[(row0 + r) * 128 + c2 * 2];
            float2 hv = *(const float2*)&hist[(row0 + r) * 128 + c2 * 2];
            *(__half2*)&tgt16[r * 136 + c2 * 2] = __floats2half2_rn(tv.x, tv.y);
            *(__half2*)&hst16[r * 136 + c2 * 2] = __floats2half2_rn(hv.x, hv.y);
        }
        __syncthreads();

        uint32_t afr[8][4];
        // ---------- phase A: logits ----------
        #pragma unroll
        for (int kt = 0; kt < 8; kt++) ldmatrix_x4(afr[kt], abase_t + kt * 32);
        float p0 = 0.f, p1 = 0.f;
        #pragma unroll
        for (int nt = 0; nt < 8; nt++) {
            const int c0 = nh * 64 + nt * 8;
            float c[4] = {0.f, 0.f, 0.f, 0.f};
            const uint32_t bb = wbase + (uint32_t)c0 * 272;
            #pragma unroll
            for (int ktp = 0; ktp < 4; ktp++) {
                uint32_t bf[4];
                ldmatrix_x4(bf, bb + ktp * 64);
                mma16816(c, afr[2 * ktp],     bf[0], bf[1]);
                mma16816(c, afr[2 * ktp + 1], bf[2], bf[3]);
            }
            float2 wb2 = *(const float2*)&Wb[c0 + 2 * q];
            float2 h0 = __half22float2(*(const __half2*)&hst16[r0 * 136 + c0 + 2 * q]);
            float2 h1 = __half22float2(*(const __half2*)&hst16[r1 * 136 + c0 + 2 * q]);
            p0 += (c[0] + wb2.x) * h0.x + (c[1] + wb2.y) * h0.y;
            p1 += (c[2] + wb2.x) * h1.x + (c[3] + wb2.y) * h1.y;
        }
        p0 += __shfl_xor_sync(~0u, p0, 1); p0 += __shfl_xor_sync(~0u, p0, 2);
        p1 += __shfl_xor_sync(~0u, p1, 1); p1 += __shfl_xor_sync(~0u, p1, 2);
        if (q == 0) {
            lgp[nh * 64 + mt * 16 + l4] = p0;
            lgp[nh * 64 + mt * 16 + l4 + 8] = p1;
        }

        // ---------- phase B: xu/xr/xg ----------
        #pragma unroll
        for (int kt = 0; kt < 8; kt++) ldmatrix_x4(afr[kt], abase_h + kt * 32);
        #pragma unroll
        for (int nt = 0; nt < 24; nt++) {
            const int gc = nh * 192 + nt * 8;
            const int m = gc >> 7, cc = gc & 127;
            const float* Bv = (m == 0) ? xub : (m == 1) ? xrb : xgb;
            float2 bb2 = *(const float2*)&Bv[cc + 2 * q];
            float c[4] = {bb2.x, bb2.y, bb2.x, bb2.y};
            const uint32_t bb = wbase + (uint32_t)(m + 1) * (K1_WSM_MAT * 2) + (uint32_t)cc * 272;
            #pragma unroll
            for (int ktp = 0; ktp < 4; ktp++) {
                uint32_t bf[4];
                ldmatrix_x4(bf, bb + ktp * 64);
                mma16816(c, afr[2 * ktp],     bf[0], bf[1]);
                mma16816(c, afr[2 * ktp + 1], bf[2], bf[3]);
            }
            size_t g0 = (row0 + r0) * 384 + gc + 2 * q;
            *(uint32_t*)&g_xall16[g0]           = f2h2(c[0], c[1]);
            *(uint32_t*)&g_xall16[g0 + 8 * 384] = f2h2(c[2], c[3]);
        }
        __syncthreads();
        if (t < 64) g_logits[row0 + t] = lgp[t] + lgp[64 + t];
    }
}

// ================= K2: softmax over T =================
__global__ void k2_softmax()
{
    __shared__ float red[256];
    const int b = blockIdx.x, t = threadIdx.x;
    float v = (t < 200) ? g_logits[b * 200 + t] : -1e30f;
    red[t] = v; __syncthreads();
    for (int s = 128; s; s >>= 1) { if (t < s) red[t] = fmaxf(red[t], red[t + s]); __syncthreads(); }
    float mx = red[0]; __syncthreads();
    float e = (t < 200) ? __expf(v - mx) : 0.f;
    red[t] = e; __syncthreads();
    for (int s = 128; s; s >>= 1) { if (t < s) red[t] += red[t + s]; __syncthreads(); }
    float inv = __fdividef(1.f, red[0]);
    if (t < 200) g_att[b * 200 + t] = e * inv;
}

// ================= K3: GRU scan, register weight fragments =================
// grid 64, block 256. CTA owns 16 batch rows. Double-buffered h tile, 1 sync/step.
#define K3_HBUF 4352   // 16*136 halves = bytes per buffer

__global__ __launch_bounds__(256) void k3_scan(
    const float* __restrict__ huw, const float* __restrict__ hub,
    const float* __restrict__ hrw, const float* __restrict__ hrb,
    const float* __restrict__ hgw, const float* __restrict__ hgb)
{
    __shared__ __align__(16) __half hsm[2 * 16 * 136];
    const int t = threadIdx.x, w = t >> 5, lane = t & 31;
    const int q = lane & 3, l4 = lane >> 2;
    const size_t rowb = (size_t)blockIdx.x * 16;
    const size_t br0 = rowb + l4, br1 = rowb + l4 + 8;

    uint32_t bfr[6][8][2];
    float2 bias2[6];
    #pragma unroll
    for (int j = 0; j < 6; j++) {
        const int g = j >> 1, hf = j & 1;
        const float* W  = (g == 0) ? huw : (g == 1) ? hrw : hgw;
        const float* Bv = (g == 0) ? hub : (g == 1) ? hrb : hgb;
        const int n = 16 * w + 8 * hf + l4;
        bias2[j] = *(const float2*)&Bv[16 * w + 8 * hf + 2 * q];
        #pragma unroll
        for (int kt = 0; kt < 8; kt++) {
            float2 wa = *(const float2*)&W[n * 128 + kt * 16 + 2 * q];
            float2 wb = *(const float2*)&W[n * 128 + kt * 16 + 2 * q + 8];
            bfr[j][kt][0] = f2h2(wa.x, wa.y);
            bfr[j][kt][1] = f2h2(wb.x, wb.y);
        }
    }
    for (int i = t; i < 2 * 16 * 136; i += 256) hsm[i] = __float2half(0.f);

    float hm[2][4] = {{0.f,0.f,0.f,0.f},{0.f,0.f,0.f,0.f}};
    uint32_t xp[6][2]; float at[2];
    #pragma unroll
    for (int j = 0; j < 6; j++) {
        const int g = j >> 1, hf = j & 1;
        const size_t col = (size_t)g * 128 + 16 * w + 8 * hf + 2 * q;
        xp[j][0] = *(const uint32_t*)&g_xall16[(br0 * 200) * 384 + col];
        xp[j][1] = *(const uint32_t*)&g_xall16[(br1 * 200) * 384 + col];
    }
    at[0] = g_att[br0 * 200]; at[1] = g_att[br1 * 200];
    __syncthreads();

    const uint32_t hb0 = smem_u32(hsm) + (lane & 15) * 272 + (lane >> 4) * 16;

    for (int step = 0; step < 200; step++) {
        const int rb = step & 1, wb = 1 - rb;
        float acc[6][4];
        #pragma unroll
        for (int j = 0; j < 4; j++) {
            float2 x0 = __half22float2(*(__half2*)&xp[j][0]);
            float2 x1 = __half22float2(*(__half2*)&xp[j][1]);
            acc[j][0] = x0.x; acc[j][1] = x0.y; acc[j][2] = x1.x; acc[j][3] = x1.y;
        }
        float xg2[2][4];
        #pragma unroll
        for (int hf = 0; hf < 2; hf++) {
            float2 x0 = __half22float2(*(__half2*)&xp[4 + hf][0]);
            float2 x1 = __half22float2(*(__half2*)&xp[4 + hf][1]);
            xg2[hf][0] = x0.x; xg2[hf][1] = x0.y; xg2[hf][2] = x1.x; xg2[hf][3] = x1.y;
            acc[4 + hf][0] = acc[4 + hf][1] = acc[4 + hf][2] = acc[4 + hf][3] = 0.f;
        }
        const float a0 = at[0], a1 = at[1];
        if (step < 199) {
            const int s1 = step + 1;
            #pragma unroll
            for (int j = 0; j < 6; j++) {
                const int g = j >> 1, hf = j & 1;
                const size_t col = (size_t)g * 128 + 16 * w + 8 * hf + 2 * q;
                xp[j][0] = *(const uint32_t*)&g_xall16[(br0 * 200 + s1) * 384 + col];
                xp[j][1] = *(const uint32_t*)&g_xall16[(br1 * 200 + s1) * 384 + col];
            }
            at[0] = g_att[br0 * 200 + s1]; at[1] = g_att[br1 * 200 + s1];
        }
        #pragma unroll
        for (int kt = 0; kt < 8; kt++) {
            uint32_t afr[4];
            ldmatrix_x4(afr, hb0 + rb * K3_HBUF + kt * 32);
            #pragma unroll
            for (int j = 0; j < 6; j++) mma16816(acc[j], afr, bfr[j][kt][0], bfr[j][kt][1]);
        }
        float hn[2][4];
        #pragma unroll
        for (int hf = 0; hf < 2; hf++) {
            #pragma unroll
            for (int e = 0; e < 4; e++) {
                const float bU = (e & 1) ? bias2[hf].y     : bias2[hf].x;
                const float bR = (e & 1) ? bias2[2 + hf].y : bias2[2 + hf].x;
                const float bG = (e & 1) ? bias2[4 + hf].y : bias2[4 + hf].x;
                const float ae = (e < 2) ? a0 : a1;
                float u = fmaf(tanhapx(0.5f * (acc[hf][e] + bU)), 0.5f, 0.5f) * ae;
                float r = fmaf(tanhapx(0.5f * (acc[2 + hf][e] + bR)), 0.5f, 0.5f);
                float pre = xg2[hf][e] + r * (acc[4 + hf][e] + bG);
                float gg = tanhapx(pre);
                hn[hf][e] = fmaf(u, gg - hm[hf][e], hm[hf][e]);
            }
        }
        char* hw = (char*)hsm + wb * K3_HBUF;
        #pragma unroll
        for (int hf = 0; hf < 2; hf++) {
            const int cc = 16 * w + 8 * hf + 2 * q;
            *(uint32_t*)(hw + l4 * 272 + cc * 2)       = f2h2(hn[hf][0], hn[hf][1]);
            *(uint32_t*)(hw + (l4 + 8) * 272 + cc * 2) = f2h2(hn[hf][2], hn[hf][3]);
            hm[hf][0] = hn[hf][0]; hm[hf][1] = hn[hf][1];
            hm[hf][2] = hn[hf][2]; hm[hf][3] = hn[hf][3];
        }
        __syncthreads();
    }
    #pragma unroll
    for (int hf = 0; hf < 2; hf++) {
        const int cc = 16 * w + 8 * hf + 2 * q;
        *(float2*)&g_hfinal[br0 * 128 + cc] = make_float2(hm[hf][0], hm[hf][1]);
        *(float2*)&g_hfinal[br1 * 128 + cc] = make_float2(hm[hf][2], hm[hf][3]);
    }
}

// ================= K4: final linear, 4 batches/block =================
__global__ __launch_bounds__(256) void k4_out(const float* __restrict__ targets,
                                              const float* __restrict__ w,
                                              const float* __restrict__ bias,
                                              float* __restrict__ out)
{
    __shared__ __align__(16) float xs[4][260];
    const int t = threadIdx.x;
    const int b0 = blockIdx.x * 4;
    for (int i = t; i < 4 * 128; i += 256) {
        int bb = i >> 7, c = i & 127;
        xs[bb][c]       = g_hfinal[(b0 + bb) * 128 + c];
        xs[bb][128 + c] = targets[(size_t)(b0 + bb) * 200 * 128 + c];
    }
    __syncthreads();
    const int col = t & 127, grp = t >> 7;
    float acc[2];
    const float bv = bias[col];
    acc[0] = bv; acc[1] = bv;
    const float4* wr = (const float4*)(w + (size_t)col * 256);
    #pragma unroll 8
    for (int k = 0; k < 64; k++) {
        float4 wv = wr[k];
        #pragma unroll
        for (int i = 0; i < 2; i++) {
            float4 xv = *(const float4*)&xs[grp * 2 + i][k * 4];
            acc[i] += wv.x * xv.x + wv.y * xv.y + wv.z * xv.z + wv.w * xv.w;
        }
    }
    #pragma unroll
    for (int i = 0; i < 2; i++)
        out[(b0 + grp * 2 + i) * 128 + col] = acc[i];
}

extern "C" void kernel_launch(void* const* d_in, const int* in_sizes, int n_in,
                              void* d_out, int out_size)
{
    const float* targets = (const float*)d_in[0];
    const float* hist    = (const float*)d_in[1];
    const float* Ww  = (const float*)d_in[2];  const float* Wb  = (const float*)d_in[3];
    const float* xuw = (const float*)d_in[4];  const float* xub = (const float*)d_in[5];
    const float* huw = (const float*)d_in[6];  const float* hub = (const float*)d_in[7];
    const float* xrw = (const float*)d_in[8];  const float* xrb = (const float*)d_in[9];
    const float* hrw = (const float*)d_in[10]; const float* hrb = (const float*)d_in[11];
    const float* xgw = (const float*)d_in[12]; const float* xgb = (const float*)d_in[13];
    const float* hgw = (const float*)d_in[14]; const float* hgb = (const float*)d_in[15];
    const float* lnw = (const float*)d_in[16]; const float* lnb = (const float*)d_in[17];
    float* out = (float*)d_out;

    cudaFuncSetAttribute(k1_ff, cudaFuncAttributeMaxDynamicSharedMemorySize, K1_SMEM);

    k1_ff<<<400, 256, K1_SMEM>>>(targets, hist, Ww, Wb, xuw, xub, xrw, xrb, xgw, xgb);
    k2_softmax<<<1024, 256>>>();
    k3_scan<<<64, 256>>>(huw, hub, hrw, hrb, hgw, hgb);
    k4_out<<<256, 256>>>(targets, lnw, lnb, out);
}

// round 7
// speedup vs baseline: 5.0847x; 1.0256x over previous
#include <cuda_runtime.h>
#include <cuda_fp16.h>
#include <cstdint>

// B=1024, T=200, IN=H=128. rows = 204800.
__device__ __half g_xall16[(size_t)204800 * 384];   // xu|xr|xg fp16 (biases folded in k1)
__device__ float g_logits[204800];
__device__ float g_att[204800];
__device__ float g_hfinal[1024 * 128];

__device__ __forceinline__ uint32_t smem_u32(const void* p) {
    return (uint32_t)__cvta_generic_to_shared(p);
}
__device__ __forceinline__ void ldmatrix_x4(uint32_t a[4], uint32_t addr) {
    asm volatile("ldmatrix.sync.aligned.m8n8.x4.shared.b16 {%0,%1,%2,%3}, [%4];"
                 : "=r"(a[0]), "=r"(a[1]), "=r"(a[2]), "=r"(a[3]) : "r"(addr));
}
__device__ __forceinline__ void mma16816(float c[4], const uint32_t a[4], uint32_t b0, uint32_t b1) {
    asm volatile("mma.sync.aligned.m16n8k16.row.col.f32.f16.f16.f32 "
                 "{%0,%1,%2,%3},{%4,%5,%6,%7},{%8,%9},{%0,%1,%2,%3};"
                 : "+f"(c[0]), "+f"(c[1]), "+f"(c[2]), "+f"(c[3])
                 : "r"(a[0]), "r"(a[1]), "r"(a[2]), "r"(a[3]), "r"(b0), "r"(b1));
}
__device__ __forceinline__ uint32_t f2h2(float x, float y) {
    __half2 h = __floats2half2_rn(x, y);
    return *reinterpret_cast<uint32_t*>(&h);
}
__device__ __forceinline__ float tanhapx(float x) {
    float y; asm("tanh.approx.f32 %0, %1;" : "=f"(y) : "f"(x)); return y;
}

// ================= K1: logits + x projections =================
// grid 400, block 256 (8 warps). Stage 4 weight matrices fp16 in smem once, 8 tiles of 64 rows.
#define K1_WSM_MAT (128 * 136)
#define K1_TGT_OFF 139264
#define K1_HST_OFF 156672
#define K1_LGP_OFF 174080
#define K1_SMEM    174592

__global__ __launch_bounds__(256) void k1_ff(
    const float* __restrict__ targets, const float* __restrict__ hist,
    const float* __restrict__ Ww,  const float* __restrict__ Wb,
    const float* __restrict__ xuw, const float* __restrict__ xub,
    const float* __restrict__ xrw, const float* __restrict__ xrb,
    const float* __restrict__ xgw, const float* __restrict__ xgb)
{
    extern __shared__ char sm[];
    __half* wsm16 = (__half*)sm;
    __half* tgt16 = (__half*)(sm + K1_TGT_OFF);
    __half* hst16 = (__half*)(sm + K1_HST_OFF);
    float*  lgp   = (float*)(sm + K1_LGP_OFF);
    const int t = threadIdx.x;

    {
        const float* Wm[4] = {Ww, xuw, xrw, xgw};
        #pragma unroll
        for (int m = 0; m < 4; m++) {
            const float* W = Wm[m];
            __half* dst = wsm16 + m * K1_WSM_MAT;
            for (int i = t; i < 8192; i += 256) {
                int r = i >> 6, c2 = i & 63;
                float2 v = *(const float2*)&W[r * 128 + c2 * 2];
                *(__half2*)&dst[r * 136 + c2 * 2] = __floats2half2_rn(v.x, v.y);
            }
        }
    }

    const int w = t >> 5, lane = t & 31;
    const int mt = w & 3, nh = w >> 2;
    const int q = lane & 3, l4 = lane >> 2;
    const int r0 = mt * 16 + l4, r1 = r0 + 8;
    const uint32_t wbase = smem_u32(wsm16) + ((lane & 7) * 272 + (lane >> 3) * 16);
    const uint32_t abase_t = smem_u32(tgt16) + (mt * 16 + (lane & 15)) * 272 + (lane >> 4) * 16;
    const uint32_t abase_h = smem_u32(hst16) + (mt * 16 + (lane & 15)) * 272 + (lane >> 4) * 16;

    for (int it = 0; it < 8; it++) {
        const size_t row0 = ((size_t)blockIdx.x * 8 + it) * 64;
        __syncthreads();
        for (int i = t; i < 64 * 64; i += 256) {
            int r = i >> 6, c2 = i & 63;
            float2 tv = *(const float2*)&targets[(row0 + r) * 128 + c2 * 2];
            float2 hv = *(const float2*)&hist[(row0 + r) * 128 + c2 * 2];
            *(__half2*)&tgt16[r * 136 + c2 * 2] = __floats2half2_rn(tv.x, tv.y);
            *(__half2*)&hst16[r * 136 + c2 * 2] = __floats2half2_rn(hv.x, hv.y);
        }
        __syncthreads();

        uint32_t afr[8][4];
        // ---------- phase A: logits ----------
        #pragma unroll
        for (int kt = 0; kt < 8; kt++) ldmatrix_x4(afr[kt], abase_t + kt * 32);
        float p0 = 0.f, p1 = 0.f;
        #pragma unroll
        for (int nt = 0; nt < 8; nt++) {
            const int c0 = nh * 64 + nt * 8;
            float c[4] = {0.f, 0.f, 0.f, 0.f};
            const uint32_t bb = wbase + (uint32_t)c0 * 272;
            #pragma unroll
            for (int ktp = 0; ktp < 4; ktp++) {
                uint32_t bf[4];
                ldmatrix_x4(bf, bb + ktp * 64);
                mma16816(c, afr[2 * ktp],     bf[0], bf[1]);
                mma16816(c, afr[2 * ktp + 1], bf[2], bf[3]);
            }
            float2 wb2 = *(const float2*)&Wb[c0 + 2 * q];
            float2 h0 = __half22float2(*(const __half2*)&hst16[r0 * 136 + c0 + 2 * q]);
            float2 h1 = __half22float2(*(const __half2*)&hst16[r1 * 136 + c0 + 2 * q]);
            p0 += (c[0] + wb2.x) * h0.x + (c[1] + wb2.y) * h0.y;
            p1 += (c[2] + wb2.x) * h1.x + (c[3] + wb2.y) * h1.y;
        }
        p0 += __shfl_xor_sync(~0u, p0, 1); p0 += __shfl_xor_sync(~0u, p0, 2);
        p1 += __shfl_xor_sync(~0u, p1, 1); p1 += __shfl_xor_sync(~0u, p1, 2);
        if (q == 0) {
            lgp[nh * 64 + mt * 16 + l4] = p0;
            lgp[nh * 64 + mt * 16 + l4 + 8] = p1;
        }

        // ---------- phase B: xu/xr/xg ----------
        #pragma unroll
        for (int kt = 0; kt < 8; kt++) ldmatrix_x4(afr[kt], abase_h + kt * 32);
        #pragma unroll
        for (int nt = 0; nt < 24; nt++) {
            const int gc = nh * 192 + nt * 8;
            const int m = gc >> 7, cc = gc & 127;
            const float* Bv = (m == 0) ? xub : (m == 1) ? xrb : xgb;
            float2 bb2 = *(const float2*)&Bv[cc + 2 * q];
            float c[4] = {bb2.x, bb2.y, bb2.x, bb2.y};
            const uint32_t bb = wbase + (uint32_t)(m + 1) * (K1_WSM_MAT * 2) + (uint32_t)cc * 272;
            #pragma unroll
            for (int ktp = 0; ktp < 4; ktp++) {
                uint32_t bf[4];
                ldmatrix_x4(bf, bb + ktp * 64);
                mma16816(c, afr[2 * ktp],     bf[0], bf[1]);
                mma16816(c, afr[2 * ktp + 1], bf[2], bf[3]);
            }
            size_t g0 = (row0 + r0) * 384 + gc + 2 * q;
            *(uint32_t*)&g_xall16[g0]           = f2h2(c[0], c[1]);
            *(uint32_t*)&g_xall16[g0 + 8 * 384] = f2h2(c[2], c[3]);
        }
        __syncthreads();
        if (t < 64) g_logits[row0 + t] = lgp[t] + lgp[64 + t];
    }
}

// ================= K2: softmax over T =================
__global__ void k2_softmax()
{
    __shared__ float red[256];
    const int b = blockIdx.x, t = threadIdx.x;
    float v = (t < 200) ? g_logits[b * 200 + t] : -1e30f;
    red[t] = v; __syncthreads();
    for (int s = 128; s; s >>= 1) { if (t < s) red[t] = fmaxf(red[t], red[t + s]); __syncthreads(); }
    float mx = red[0]; __syncthreads();
    float e = (t < 200) ? __expf(v - mx) : 0.f;
    red[t] = e; __syncthreads();
    for (int s = 128; s; s >>= 1) { if (t < s) red[t] += red[t + s]; __syncthreads(); }
    float inv = __fdividef(1.f, red[0]);
    if (t < 200) g_att[b * 200 + t] = e * inv;
}

// ================= K3: GRU scan, 16 warps, warp owns 8 cols x 3 gates =================
#define K3_HBUF 4352   // bytes per h buffer (16*136 halves)

__global__ __launch_bounds__(512) void k3_scan(
    const float* __restrict__ huw, const float* __restrict__ hub,
    const float* __restrict__ hrw, const float* __restrict__ hrb,
    const float* __restrict__ hgw, const float* __restrict__ hgb)
{
    __shared__ __align__(16) __half hsm[2 * 16 * 136];
    const int t = threadIdx.x, w = t >> 5, lane = t & 31;
    const int q = lane & 3, l4 = lane >> 2;
    const int c0 = 8 * w;                       // warp's 8-column group
    const size_t rowb = (size_t)blockIdx.x * 16;
    const size_t br0 = rowb + l4, br1 = rowb + l4 + 8;

    // weight B-fragments: 3 gates x 8 ktiles x 2 regs
    uint32_t bfr[3][8][2];
    float2 bias2[3];
    #pragma unroll
    for (int g = 0; g < 3; g++) {
        const float* W  = (g == 0) ? huw : (g == 1) ? hrw : hgw;
        const float* Bv = (g == 0) ? hub : (g == 1) ? hrb : hgb;
        const int n = c0 + l4;
        bias2[g] = *(const float2*)&Bv[c0 + 2 * q];
        #pragma unroll
        for (int kt = 0; kt < 8; kt++) {
            float2 wa = *(const float2*)&W[n * 128 + kt * 16 + 2 * q];
            float2 wb = *(const float2*)&W[n * 128 + kt * 16 + 2 * q + 8];
            bfr[g][kt][0] = f2h2(wa.x, wa.y);
            bfr[g][kt][1] = f2h2(wb.x, wb.y);
        }
    }
    for (int i = t; i < 2 * 16 * 136; i += 512) hsm[i] = __float2half(0.f);

    float hm[4] = {0.f, 0.f, 0.f, 0.f};
    uint32_t xp[3][2]; float at[2];
    #pragma unroll
    for (int g = 0; g < 3; g++) {
        const size_t col = (size_t)g * 128 + c0 + 2 * q;
        xp[g][0] = *(const uint32_t*)&g_xall16[(br0 * 200) * 384 + col];
        xp[g][1] = *(const uint32_t*)&g_xall16[(br1 * 200) * 384 + col];
    }
    at[0] = g_att[br0 * 200]; at[1] = g_att[br1 * 200];
    __syncthreads();

    const uint32_t hb0 = smem_u32(hsm) + (lane & 15) * 272 + (lane >> 4) * 16;

    for (int step = 0; step < 200; step++) {
        const int rb = step & 1, wbuf = 1 - rb;
        float accu[4], accr[4], accg[4], xg4[4];
        {
            float2 x0 = __half22float2(*(__half2*)&xp[0][0]);
            float2 x1 = __half22float2(*(__half2*)&xp[0][1]);
            accu[0] = x0.x; accu[1] = x0.y; accu[2] = x1.x; accu[3] = x1.y;
            x0 = __half22float2(*(__half2*)&xp[1][0]);
            x1 = __half22float2(*(__half2*)&xp[1][1]);
            accr[0] = x0.x; accr[1] = x0.y; accr[2] = x1.x; accr[3] = x1.y;
            x0 = __half22float2(*(__half2*)&xp[2][0]);
            x1 = __half22float2(*(__half2*)&xp[2][1]);
            xg4[0] = x0.x; xg4[1] = x0.y; xg4[2] = x1.x; xg4[3] = x1.y;
            accg[0] = accg[1] = accg[2] = accg[3] = 0.f;
        }
        const float a0 = at[0], a1 = at[1];
        if (step < 199) {                       // prefetch next step
            const int s1 = step + 1;
            #pragma unroll
            for (int g = 0; g < 3; g++) {
                const size_t col = (size_t)g * 128 + c0 + 2 * q;
                xp[g][0] = *(const uint32_t*)&g_xall16[(br0 * 200 + s1) * 384 + col];
                xp[g][1] = *(const uint32_t*)&g_xall16[(br1 * 200 + s1) * 384 + col];
            }
            at[0] = g_att[br0 * 200 + s1]; at[1] = g_att[br1 * 200 + s1];
        }
        #pragma unroll
        for (int kt = 0; kt < 8; kt++) {
            uint32_t afr[4];
            ldmatrix_x4(afr, hb0 + rb * K3_HBUF + kt * 32);
            mma16816(accu, afr, bfr[0][kt][0], bfr[0][kt][1]);
            mma16816(accr, afr, bfr[1][kt][0], bfr[1][kt][1]);
            mma16816(accg, afr, bfr[2][kt][0], bfr[2][kt][1]);
        }
        float hn[4];
        #pragma unroll
        for (int e = 0; e < 4; e++) {
            const float bU = (e & 1) ? bias2[0].y : bias2[0].x;
            const float bR = (e & 1) ? bias2[1].y : bias2[1].x;
            const float bG = (e & 1) ? bias2[2].y : bias2[2].x;
            const float ae = (e < 2) ? a0 : a1;
            float u = fmaf(tanhapx(0.5f * (accu[e] + bU)), 0.5f, 0.5f) * ae;
            float r = fmaf(tanhapx(0.5f * (accr[e] + bR)), 0.5f, 0.5f);
            float pre = xg4[e] + r * (accg[e] + bG);
            float gg = tanhapx(pre);
            hn[e] = fmaf(u, gg - hm[e], hm[e]);
        }
        char* hw = (char*)hsm + wbuf * K3_HBUF;
        *(uint32_t*)(hw + l4 * 272 + (c0 + 2 * q) * 2)       = f2h2(hn[0], hn[1]);
        *(uint32_t*)(hw + (l4 + 8) * 272 + (c0 + 2 * q) * 2) = f2h2(hn[2], hn[3]);
        hm[0] = hn[0]; hm[1] = hn[1]; hm[2] = hn[2]; hm[3] = hn[3];
        __syncthreads();
    }
    *(float2*)&g_hfinal[br0 * 128 + c0 + 2 * q] = make_float2(hm[0], hm[1]);
    *(float2*)&g_hfinal[br1 * 128 + c0 + 2 * q] = make_float2(hm[2], hm[3]);
}

// ================= K4: final linear, 8 batches/block (grid 128) =================
__global__ __launch_bounds__(256) void k4_out(const float* __restrict__ targets,
                                              const float* __restrict__ w,
                                              const float* __restrict__ bias,
                                              float* __restrict__ out)
{
    __shared__ __align__(16) float xs[8][260];
    const int t = threadIdx.x;
    const int b0 = blockIdx.x * 8;
    for (int i = t; i < 8 * 128; i += 256) {
        int bb = i >> 7, c = i & 127;
        xs[bb][c]       = g_hfinal[(b0 + bb) * 128 + c];
        xs[bb][128 + c] = targets[(size_t)(b0 + bb) * 200 * 128 + c];
    }
    __syncthreads();
    const int col = t & 127, grp = t >> 7;
    float acc[4];
    const float bv = bias[col];
    #pragma unroll
    for (int i = 0; i < 4; i++) acc[i] = bv;
    const float4* wr = (const float4*)(w + (size_t)col * 256);
    #pragma unroll 4
    for (int k = 0; k < 64; k++) {
        float4 wv = wr[k];
        #pragma unroll
        for (int i = 0; i < 4; i++) {
            float4 xv = *(const float4*)&xs[grp * 4 + i][k * 4];
            acc[i] += wv.x * xv.x + wv.y * xv.y + wv.z * xv.z + wv.w * xv.w;
        }
    }
    #pragma unroll
    for (int i = 0; i < 4; i++)
        out[(b0 + grp * 4 + i) * 128 + col] = acc[i];
}

extern "C" void kernel_launch(void* const* d_in, const int* in_sizes, int n_in,
                              void* d_out, int out_size)
{
    const float* targets = (const float*)d_in[0];
    const float* hist    = (const float*)d_in[1];
    const float* Ww  = (const float*)d_in[2];  const float* Wb  = (const float*)d_in[3];
    const float* xuw = (const float*)d_in[4];  const float* xub = (const float*)d_in[5];
    const float* huw = (const float*)d_in[6];  const float* hub = (const float*)d_in[7];
    const float* hrw = (const float*)d_in[10]; const float* hrb = (const float*)d_in[11];
    const float* xrw = (const float*)d_in[8];  const float* xrb = (const float*)d_in[9];
    const float* xgw = (const float*)d_in[12]; const float* xgb = (const float*)d_in[13];
    const float* hgw = (const float*)d_in[14]; const float* hgb = (const float*)d_in[15];
    const float* lnw = (const float*)d_in[16]; const float* lnb = (const float*)d_in[17];
    float* out = (float*)d_out;

    cudaFuncSetAttribute(k1_ff, cudaFuncAttributeMaxDynamicSharedMemorySize, K1_SMEM);

    k1_ff<<<400, 256, K1_SMEM>>>(targets, hist, Ww, Wb, xuw, xub, xrw, xrb, xgw, xgb);
    k2_softmax<<<1024, 256>>>();
    k3_scan<<<64, 512>>>(huw, hub, hrw, hrb, hgw, hgb);
    k4_out<<<128, 256>>>(targets, lnw, lnb, out);
}

// round 8
// speedup vs baseline: 5.5142x; 1.0845x over previous
#include <cuda_runtime.h>
#include <cuda_fp16.h>
#include <cstdint>

// B=1024, T=200, IN=H=128. rows = 204800.
__device__ __half g_xall16[(size_t)204800 * 384];   // [flat row b*200+t][xu|xr|xg] fp16, biases folded
__device__ float g_logits[204800];
__device__ float g_att[204800];
__device__ float g_hfinal[1024 * 128];

__device__ __forceinline__ uint32_t smem_u32(const void* p) {
    return (uint32_t)__cvta_generic_to_shared(p);
}
__device__ __forceinline__ void ldmatrix_x4(uint32_t a[4], uint32_t addr) {
    asm volatile("ldmatrix.sync.aligned.m8n8.x4.shared.b16 {%0,%1,%2,%3}, [%4];"
                 : "=r"(a[0]), "=r"(a[1]), "=r"(a[2]), "=r"(a[3]) : "r"(addr));
}
__device__ __forceinline__ void mma16816(float c[4], const uint32_t a[4], uint32_t b0, uint32_t b1) {
    asm volatile("mma.sync.aligned.m16n8k16.row.col.f32.f16.f16.f32 "
                 "{%0,%1,%2,%3},{%4,%5,%6,%7},{%8,%9},{%0,%1,%2,%3};"
                 : "+f"(c[0]), "+f"(c[1]), "+f"(c[2]), "+f"(c[3])
                 : "r"(a[0]), "r"(a[1]), "r"(a[2]), "r"(a[3]), "r"(b0), "r"(b1));
}
__device__ __forceinline__ uint32_t f2h2(float x, float y) {
    __half2 h = __floats2half2_rn(x, y);
    return *reinterpret_cast<uint32_t*>(&h);
}
__device__ __forceinline__ float tanhapx(float x) {
    float y; asm("tanh.approx.f32 %0, %1;" : "=f"(y) : "f"(x)); return y;
}

// ================= K1: logits + x projections =================
// grid 400, block 256 (8 warps). Stage 4 weight matrices fp16 in smem once, 8 tiles of 64 rows.
// Phase-B results staged per-warp in smem, flushed as 384B-contiguous rows.
#define K1_WSM_MAT (128 * 136)
#define K1_TGT_OFF 139264
#define K1_HST_OFF 156672
#define K1_LGP_OFF 174080
#define K1_SWB_OFF 174592          // 8 warps x 16 rows x 100 uint32 = 51200 B
#define K1_SMEM    225792

__global__ __launch_bounds__(256) void k1_ff(
    const float* __restrict__ targets, const float* __restrict__ hist,
    const float* __restrict__ Ww,  const float* __restrict__ Wb,
    const float* __restrict__ xuw, const float* __restrict__ xub,
    const float* __restrict__ xrw, const float* __restrict__ xrb,
    const float* __restrict__ xgw, const float* __restrict__ xgb)
{
    extern __shared__ char sm[];
    __half* wsm16 = (__half*)sm;
    __half* tgt16 = (__half*)(sm + K1_TGT_OFF);
    __half* hst16 = (__half*)(sm + K1_HST_OFF);
    float*  lgp   = (float*)(sm + K1_LGP_OFF);
    const int t = threadIdx.x;

    {
        const float* Wm[4] = {Ww, xuw, xrw, xgw};
        #pragma unroll
        for (int m = 0; m < 4; m++) {
            const float* W = Wm[m];
            __half* dst = wsm16 + m * K1_WSM_MAT;
            for (int i = t; i < 8192; i += 256) {
                int r = i >> 6, c2 = i & 63;
                float2 v = *(const float2*)&W[r * 128 + c2 * 2];
                *(__half2*)&dst[r * 136 + c2 * 2] = __floats2half2_rn(v.x, v.y);
            }
        }
    }

    const int w = t >> 5, lane = t & 31;
    const int mt = w & 3, nh = w >> 2;
    const int q = lane & 3, l4 = lane >> 2;
    const int r0 = mt * 16 + l4, r1 = r0 + 8;
    uint32_t* swb = (uint32_t*)(sm + K1_SWB_OFF) + w * 1600;   // 16 x 100
    const uint32_t wbase = smem_u32(wsm16) + ((lane & 7) * 272 + (lane >> 3) * 16);
    const uint32_t abase_t = smem_u32(tgt16) + (mt * 16 + (lane & 15)) * 272 + (lane >> 4) * 16;
    const uint32_t abase_h = smem_u32(hst16) + (mt * 16 + (lane & 15)) * 272 + (lane >> 4) * 16;

    for (int it = 0; it < 8; it++) {
        const size_t row0 = ((size_t)blockIdx.x * 8 + it) * 64;
        __syncthreads();
        for (int i = t; i < 64 * 64; i += 256) {
            int r = i >> 6, c2 = i & 63;
            float2 tv = *(const float2*)&targets[(row0 + r) * 128 + c2 * 2];
            float2 hv = *(const float2*)&hist[(row0 + r) * 128 + c2 * 2];
            *(__half2*)&tgt16[r * 136 + c2 * 2] = __floats2half2_rn(tv.x, tv.y);
            *(__half2*)&hst16[r * 136 + c2 * 2] = __floats2half2_rn(hv.x, hv.y);
        }
        __syncthreads();

        uint32_t afr[8][4];
        // ---------- phase A: logits ----------
        #pragma unroll
        for (int kt = 0; kt < 8; kt++) ldmatrix_x4(afr[kt], abase_t + kt * 32);
        float p0 = 0.f, p1 = 0.f;
        #pragma unroll
        for (int nt = 0; nt < 8; nt++) {
            const int c0 = nh * 64 + nt * 8;
            float c[4] = {0.f, 0.f, 0.f, 0.f};
            const uint32_t bb = wbase + (uint32_t)c0 * 272;
            #pragma unroll
            for (int ktp = 0; ktp < 4; ktp++) {
                uint32_t bf[4];
                ldmatrix_x4(bf, bb + ktp * 64);
                mma16816(c, afr[2 * ktp],     bf[0], bf[1]);
                mma16816(c, afr[2 * ktp + 1], bf[2], bf[3]);
            }
            float2 wb2 = *(const float2*)&Wb[c0 + 2 * q];
            float2 h0 = __half22float2(*(const __half2*)&hst16[r0 * 136 + c0 + 2 * q]);
            float2 h1 = __half22float2(*(const __half2*)&hst16[r1 * 136 + c0 + 2 * q]);
            p0 += (c[0] + wb2.x) * h0.x + (c[1] + wb2.y) * h0.y;
            p1 += (c[2] + wb2.x) * h1.x + (c[3] + wb2.y) * h1.y;
        }
        p0 += __shfl_xor_sync(~0u, p0, 1); p0 += __shfl_xor_sync(~0u, p0, 2);
        p1 += __shfl_xor_sync(~0u, p1, 1); p1 += __shfl_xor_sync(~0u, p1, 2);
        if (q == 0) {
            lgp[nh * 64 + mt * 16 + l4] = p0;
            lgp[nh * 64 + mt * 16 + l4 + 8] = p1;
        }

        // ---------- phase B: xu/xr/xg -> smem stage -> coalesced flush ----------
        #pragma unroll
        for (int kt = 0; kt < 8; kt++) ldmatrix_x4(afr[kt], abase_h + kt * 32);
        #pragma unroll
        for (int nt = 0; nt < 24; nt++) {
            const int gc = nh * 192 + nt * 8;
            const int m = gc >> 7, cc = gc & 127;
            const float* Bv = (m == 0) ? xub : (m == 1) ? xrb : xgb;
            float2 bb2 = *(const float2*)&Bv[cc + 2 * q];
            float c[4] = {bb2.x, bb2.y, bb2.x, bb2.y};
            const uint32_t bb = wbase + (uint32_t)(m + 1) * (K1_WSM_MAT * 2) + (uint32_t)cc * 272;
            #pragma unroll
            for (int ktp = 0; ktp < 4; ktp++) {
                uint32_t bf[4];
                ldmatrix_x4(bf, bb + ktp * 64);
                mma16816(c, afr[2 * ktp],     bf[0], bf[1]);
                mma16816(c, afr[2 * ktp + 1], bf[2], bf[3]);
            }
            swb[l4 * 100 + nt * 4 + q]       = f2h2(c[0], c[1]);
            swb[(l4 + 8) * 100 + nt * 4 + q] = f2h2(c[2], c[3]);
        }
        __syncwarp();
        #pragma unroll 2
        for (int i = lane; i < 384; i += 32) {
            int row = i / 24, wi = i % 24;
            uint4 v = *(uint4*)&swb[row * 100 + wi * 4];
            *(uint4*)&g_xall16[(row0 + mt * 16 + row) * 384 + nh * 192 + wi * 8] = v;
        }
        __syncwarp();
        __syncthreads();
        if (t < 64) g_logits[row0 + t] = lgp[t] + lgp[64 + t];
    }
}

// ================= K2: softmax over T =================
__global__ void k2_softmax()
{
    __shared__ float red[256];
    const int b = blockIdx.x, t = threadIdx.x;
    float v = (t < 200) ? g_logits[b * 200 + t] : -1e30f;
    red[t] = v; __syncthreads();
    for (int s = 128; s; s >>= 1) { if (t < s) red[t] = fmaxf(red[t], red[t + s]); __syncthreads(); }
    float mx = red[0]; __syncthreads();
    float e = (t < 200) ? __expf(v - mx) : 0.f;
    red[t] = e; __syncthreads();
    for (int s = 128; s; s >>= 1) { if (t < s) red[t] += red[t + s]; __syncthreads(); }
    float inv = __fdividef(1.f, red[0]);
    if (t < 200) g_att[b * 200 + t] = e * inv;
}

// ================= K3: GRU scan, smem-staged coalesced x prefetch =================
#define K3_HBUF 4352           // bytes per h buffer (16*136 halves)
#define XPAD 196               // uint32 row stride in xbuf

__global__ __launch_bounds__(512) void k3_scan(
    const float* __restrict__ huw, const float* __restrict__ hub,
    const float* __restrict__ hrw, const float* __restrict__ hrb,
    const float* __restrict__ hgw, const float* __restrict__ hgb)
{
    __shared__ __align__(16) __half hsm[2 * 16 * 136];
    __shared__ __align__(16) uint32_t xbuf[2][16 * XPAD];
    __shared__ float attbuf[2][16];
    const int t = threadIdx.x, w = t >> 5, lane = t & 31;
    const int q = lane & 3, l4 = lane >> 2;
    const int c0 = 8 * w;
    const size_t rowb = (size_t)blockIdx.x * 16;
    const size_t br0 = rowb + l4, br1 = rowb + l4 + 8;

    uint32_t bfr[3][8][2];
    float2 bias2[3];
    #pragma unroll
    for (int g = 0; g < 3; g++) {
        const float* W  = (g == 0) ? huw : (g == 1) ? hrw : hgw;
        const float* Bv = (g == 0) ? hub : (g == 1) ? hrb : hgb;
        const int n = c0 + l4;
        bias2[g] = *(const float2*)&Bv[c0 + 2 * q];
        #pragma unroll
        for (int kt = 0; kt < 8; kt++) {
            float2 wa = *(const float2*)&W[n * 128 + kt * 16 + 2 * q];
            float2 wb = *(const float2*)&W[n * 128 + kt * 16 + 2 * q + 8];
            bfr[g][kt][0] = f2h2(wa.x, wa.y);
            bfr[g][kt][1] = f2h2(wb.x, wb.y);
        }
    }
    for (int i = t; i < 2 * 16 * 136; i += 512) hsm[i] = __float2half(0.f);

    // initial x/att fill for step 0 (coalesced: 16 contiguous 768B rows)
    for (int i = t; i < 3072; i += 512) {
        int row = i / 192, col = i % 192;
        xbuf[0][row * XPAD + col] =
            *(const uint32_t*)&g_xall16[((rowb + row) * 200) * 384 + col * 2];
    }
    if (t < 16) attbuf[0][t] = g_att[(rowb + t) * 200];
    __syncthreads();

    float hm[4] = {0.f, 0.f, 0.f, 0.f};
    const uint32_t hb0 = smem_u32(hsm) + (lane & 15) * 272 + (lane >> 4) * 16;
    const int pg0 = 4 * w + q;                     // colpair within gate

    for (int step = 0; step < 200; step++) {
        const int rb = step & 1, wbuf = 1 - rb;
        // gather this step's x from smem (conflict-free)
        float au[4], ar[4], xg4[4];
        {
            float2 v0 = __half22float2(*(__half2*)&xbuf[rb][l4 * XPAD + pg0]);
            float2 v1 = __half22float2(*(__half2*)&xbuf[rb][(l4 + 8) * XPAD + pg0]);
            au[0] = v0.x; au[1] = v0.y; au[2] = v1.x; au[3] = v1.y;
            v0 = __half22float2(*(__half2*)&xbuf[rb][l4 * XPAD + 64 + pg0]);
            v1 = __half22float2(*(__half2*)&xbuf[rb][(l4 + 8) * XPAD + 64 + pg0]);
            ar[0] = v0.x; ar[1] = v0.y; ar[2] = v1.x; ar[3] = v1.y;
            v0 = __half22float2(*(__half2*)&xbuf[rb][l4 * XPAD + 128 + pg0]);
            v1 = __half22float2(*(__half2*)&xbuf[rb][(l4 + 8) * XPAD + 128 + pg0]);
            xg4[0] = v0.x; xg4[1] = v0.y; xg4[2] = v1.x; xg4[3] = v1.y;
        }
        const float a0 = attbuf[rb][l4], a1 = attbuf[rb][l4 + 8];

        // prefetch next step's x/att (coalesced LDG, consumed at loop end)
        uint32_t xr6[6]; float attr = 0.f;
        if (step < 199) {
            #pragma unroll
            for (int j = 0; j < 6; j++) {
                int idx = t + j * 512;
                int row = idx / 192, col = idx % 192;
                xr6[j] = *(const uint32_t*)&g_xall16[((rowb + row) * 200 + step + 1) * 384 + col * 2];
            }
            if (t < 16) attr = g_att[(rowb + t) * 200 + step + 1];
        }

        // mma: split accumulators to halve the dependent chain
        float bu[4] = {0,0,0,0}, br_[4] = {0,0,0,0}, ag[4] = {0,0,0,0}, ag2[4] = {0,0,0,0};
        #pragma unroll
        for (int kt = 0; kt < 4; kt++) {
            uint32_t afr[4];
            ldmatrix_x4(afr, hb0 + rb * K3_HBUF + kt * 32);
            mma16816(au,  afr, bfr[0][kt][0], bfr[0][kt][1]);
            mma16816(ar,  afr, bfr[1][kt][0], bfr[1][kt][1]);
            mma16816(ag,  afr, bfr[2][kt][0], bfr[2][kt][1]);
        }
        #pragma unroll
        for (int kt = 4; kt < 8; kt++) {
            uint32_t afr[4];
            ldmatrix_x4(afr, hb0 + rb * K3_HBUF + kt * 32);
            mma16816(bu,  afr, bfr[0][kt][0], bfr[0][kt][1]);
            mma16816(br_, afr, bfr[1][kt][0], bfr[1][kt][1]);
            mma16816(ag2, afr, bfr[2][kt][0], bfr[2][kt][1]);
        }
        float hn[4];
        #pragma unroll
        for (int e = 0; e < 4; e++) {
            const float bU = (e & 1) ? bias2[0].y : bias2[0].x;
            const float bR = (e & 1) ? bias2[1].y : bias2[1].x;
            const float bG = (e & 1) ? bias2[2].y : bias2[2].x;
            const float ae = (e < 2) ? a0 : a1;
            float u = fmaf(tanhapx(0.5f * (au[e] + bu[e] + bU)), 0.5f, 0.5f) * ae;
            float r = fmaf(tanhapx(0.5f * (ar[e] + br_[e] + bR)), 0.5f, 0.5f);
            float pre = xg4[e] + r * (ag[e] + ag2[e] + bG);
            float gg = tanhapx(pre);
            hn[e] = fmaf(u, gg - hm[e], hm[e]);
        }
        // publish h(t+1) and x(t+1) together under one barrier
        char* hw = (char*)hsm + wbuf * K3_HBUF;
        *(uint32_t*)(hw + l4 * 272 + (c0 + 2 * q) * 2)       = f2h2(hn[0], hn[1]);
        *(uint32_t*)(hw + (l4 + 8) * 272 + (c0 + 2 * q) * 2) = f2h2(hn[2], hn[3]);
        hm[0] = hn[0]; hm[1] = hn[1]; hm[2] = hn[2]; hm[3] = hn[3];
        if (step < 199) {
            #pragma unroll
            for (int j = 0; j < 6; j++) {
                int idx = t + j * 512;
                int row = idx / 192, col = idx % 192;
                xbuf[wbuf][row * XPAD + col] = xr6[j];
            }
            if (t < 16) attbuf[wbuf][t] = attr;
        }
        __syncthreads();
    }
    *(float2*)&g_hfinal[br0 * 128 + c0 + 2 * q] = make_float2(hm[0], hm[1]);
    *(float2*)&g_hfinal[br1 * 128 + c0 + 2 * q] = make_float2(hm[2], hm[3]);
}

// ================= K4: final linear, 8 batches/block =================
__global__ __launch_bounds__(256) void k4_out(const float* __restrict__ targets,
                                              const float* __restrict__ w,
                                              const float* __restrict__ bias,
                                              float* __restrict__ out)
{
    __shared__ __align__(16) float xs[8][260];
    const int t = threadIdx.x;
    const int b0 = blockIdx.x * 8;
    for (int i = t; i < 8 * 128; i += 256) {
        int bb = i >> 7, c = i & 127;
        xs[bb][c]       = g_hfinal[(b0 + bb) * 128 + c];
        xs[bb][128 + c] = targets[(size_t)(b0 + bb) * 200 * 128 + c];
    }
    __syncthreads();
    const int col = t & 127, grp = t >> 7;
    float acc[4];
    const float bv = bias[col];
    #pragma unroll
    for (int i = 0; i < 4; i++) acc[i] = bv;
    const float4* wr = (const float4*)(w + (size_t)col * 256);
    #pragma unroll 4
    for (int k = 0; k < 64; k++) {
        float4 wv = wr[k];
        #pragma unroll
        for (int i = 0; i < 4; i++) {
            float4 xv = *(const float4*)&xs[grp * 4 + i][k * 4];
            acc[i] += wv.x * xv.x + wv.y * xv.y + wv.z * xv.z + wv.w * xv.w;
        }
    }
    #pragma unroll
    for (int i = 0; i < 4; i++)
        out[(b0 + grp * 4 + i) * 128 + col] = acc[i];
}

extern "C" void kernel_launch(void* const* d_in, const int* in_sizes, int n_in,
                              void* d_out, int out_size)
{
    const float* targets = (const float*)d_in[0];
    const float* hist    = (const float*)d_in[1];
    const float* Ww  = (const float*)d_in[2];  const float* Wb  = (const float*)d_in[3];
    const float* xuw = (const float*)d_in[4];  const float* xub = (const float*)d_in[5];
    const float* huw = (const float*)d_in[6];  const float* hub = (const float*)d_in[7];
    const float* xrw = (const float*)d_in[8];  const float* xrb = (const float*)d_in[9];
    const float* hrw = (const float*)d_in[10]; const float* hrb = (const float*)d_in[11];
    const float* xgw = (const float*)d_in[12]; const float* xgb = (const float*)d_in[13];
    const float* hgw = (const float*)d_in[14]; const float* hgb = (const float*)d_in[15];
    const float* lnw = (const float*)d_in[16]; const float* lnb = (const float*)d_in[17];
    float* out = (float*)d_out;

    cudaFuncSetAttribute(k1_ff, cudaFuncAttributeMaxDynamicSharedMemorySize, K1_SMEM);

    k1_ff<<<400, 256, K1_SMEM>>>(targets, hist, Ww, Wb, xuw, xub, xrw, xrb, xgw, xgb);
    k2_softmax<<<1024, 256>>>();
    k3_scan<<<64, 512>>>(huw, hub, hrw, hrb, hgw, hgb);
    k4_out<<<128, 256>>>(targets, lnw, lnb, out);
}

// round 9
// speedup vs baseline: 5.6813x; 1.0303x over previous
#include <cuda_runtime.h>
#include <cuda_fp16.h>
#include <cstdint>

// B=1024, T=200, IN=H=128. rows = 204800.
__device__ __half g_xall16[(size_t)204800 * 384];   // [flat row][xu|xr|xg] fp16, biases folded
__device__ float g_logits[204800];
__device__ float g_att[204800];

__device__ __forceinline__ uint32_t smem_u32(const void* p) {
    return (uint32_t)__cvta_generic_to_shared(p);
}
__device__ __forceinline__ void ldmatrix_x4(uint32_t a[4], uint32_t addr) {
    asm volatile("ldmatrix.sync.aligned.m8n8.x4.shared.b16 {%0,%1,%2,%3}, [%4];"
                 : "=r"(a[0]), "=r"(a[1]), "=r"(a[2]), "=r"(a[3]) : "r"(addr));
}
__device__ __forceinline__ void mma16816(float c[4], const uint32_t a[4], uint32_t b0, uint32_t b1) {
    asm volatile("mma.sync.aligned.m16n8k16.row.col.f32.f16.f16.f32 "
                 "{%0,%1,%2,%3},{%4,%5,%6,%7},{%8,%9},{%0,%1,%2,%3};"
                 : "+f"(c[0]), "+f"(c[1]), "+f"(c[2]), "+f"(c[3])
                 : "r"(a[0]), "r"(a[1]), "r"(a[2]), "r"(a[3]), "r"(b0), "r"(b1));
}
__device__ __forceinline__ uint32_t f2h2(float x, float y) {
    __half2 h = __floats2half2_rn(x, y);
    return *reinterpret_cast<uint32_t*>(&h);
}
__device__ __forceinline__ float tanhapx(float x) {
    float y; asm("tanh.approx.f32 %0, %1;" : "=f"(y) : "f"(x)); return y;
}

// ================= K1: logits + x projections (unchanged from R7) =================
#define K1_WSM_MAT (128 * 136)
#define K1_TGT_OFF 139264
#define K1_HST_OFF 156672
#define K1_LGP_OFF 174080
#define K1_SWB_OFF 174592
#define K1_SMEM    225792

__global__ __launch_bounds__(256) void k1_ff(
    const float* __restrict__ targets, const float* __restrict__ hist,
    const float* __restrict__ Ww,  const float* __restrict__ Wb,
    const float* __restrict__ xuw, const float* __restrict__ xub,
    const float* __restrict__ xrw, const float* __restrict__ xrb,
    const float* __restrict__ xgw, const float* __restrict__ xgb)
{
    extern __shared__ char sm[];
    __half* wsm16 = (__half*)sm;
    __half* tgt16 = (__half*)(sm + K1_TGT_OFF);
    __half* hst16 = (__half*)(sm + K1_HST_OFF);
    float*  lgp   = (float*)(sm + K1_LGP_OFF);
    const int t = threadIdx.x;

    {
        const float* Wm[4] = {Ww, xuw, xrw, xgw};
        #pragma unroll
        for (int m = 0; m < 4; m++) {
            const float* W = Wm[m];
            __half* dst = wsm16 + m * K1_WSM_MAT;
            for (int i = t; i < 8192; i += 256) {
                int r = i >> 6, c2 = i & 63;
                float2 v = *(const float2*)&W[r * 128 + c2 * 2];
                *(__half2*)&dst[r * 136 + c2 * 2] = __floats2half2_rn(v.x, v.y);
            }
        }
    }

    const int w = t >> 5, lane = t & 31;
    const int mt = w & 3, nh = w >> 2;
    const int q = lane & 3, l4 = lane >> 2;
    const int r0 = mt * 16 + l4, r1 = r0 + 8;
    uint32_t* swb = (uint32_t*)(sm + K1_SWB_OFF) + w * 1600;
    const uint32_t wbase = smem_u32(wsm16) + ((lane & 7) * 272 + (lane >> 3) * 16);
    const uint32_t abase_t = smem_u32(tgt16) + (mt * 16 + (lane & 15)) * 272 + (lane >> 4) * 16;
    const uint32_t abase_h = smem_u32(hst16) + (mt * 16 + (lane & 15)) * 272 + (lane >> 4) * 16;

    for (int it = 0; it < 8; it++) {
        const size_t row0 = ((size_t)blockIdx.x * 8 + it) * 64;
        __syncthreads();
        for (int i = t; i < 64 * 64; i += 256) {
            int r = i >> 6, c2 = i & 63;
            float2 tv = *(const float2*)&targets[(row0 + r) * 128 + c2 * 2];
            float2 hv = *(const float2*)&hist[(row0 + r) * 128 + c2 * 2];
            *(__half2*)&tgt16[r * 136 + c2 * 2] = __floats2half2_rn(tv.x, tv.y);
            *(__half2*)&hst16[r * 136 + c2 * 2] = __floats2half2_rn(hv.x, hv.y);
        }
        __syncthreads();

        uint32_t afr[8][4];
        #pragma unroll
        for (int kt = 0; kt < 8; kt++) ldmatrix_x4(afr[kt], abase_t + kt * 32);
        float p0 = 0.f, p1 = 0.f;
        #pragma unroll
        for (int nt = 0; nt < 8; nt++) {
            const int c0 = nh * 64 + nt * 8;
            float c[4] = {0.f, 0.f, 0.f, 0.f};
            const uint32_t bb = wbase + (uint32_t)c0 * 272;
            #pragma unroll
            for (int ktp = 0; ktp < 4; ktp++) {
                uint32_t bf[4];
                ldmatrix_x4(bf, bb + ktp * 64);
                mma16816(c, afr[2 * ktp],     bf[0], bf[1]);
                mma16816(c, afr[2 * ktp + 1], bf[2], bf[3]);
            }
            float2 wb2 = *(const float2*)&Wb[c0 + 2 * q];
            float2 h0 = __half22float2(*(const __half2*)&hst16[r0 * 136 + c0 + 2 * q]);
            float2 h1 = __half22float2(*(const __half2*)&hst16[r1 * 136 + c0 + 2 * q]);
            p0 += (c[0] + wb2.x) * h0.x + (c[1] + wb2.y) * h0.y;
            p1 += (c[2] + wb2.x) * h1.x + (c[3] + wb2.y) * h1.y;
        }
        p0 += __shfl_xor_sync(~0u, p0, 1); p0 += __shfl_xor_sync(~0u, p0, 2);
        p1 += __shfl_xor_sync(~0u, p1, 1); p1 += __shfl_xor_sync(~0u, p1, 2);
        if (q == 0) {
            lgp[nh * 64 + mt * 16 + l4] = p0;
            lgp[nh * 64 + mt * 16 + l4 + 8] = p1;
        }

        #pragma unroll
        for (int kt = 0; kt < 8; kt++) ldmatrix_x4(afr[kt], abase_h + kt * 32);
        #pragma unroll
        for (int nt = 0; nt < 24; nt++) {
            const int gc = nh * 192 + nt * 8;
            const int m = gc >> 7, cc = gc & 127;
            const float* Bv = (m == 0) ? xub : (m == 1) ? xrb : xgb;
            float2 bb2 = *(const float2*)&Bv[cc + 2 * q];
            float c[4] = {bb2.x, bb2.y, bb2.x, bb2.y};
            const uint32_t bb = wbase + (uint32_t)(m + 1) * (K1_WSM_MAT * 2) + (uint32_t)cc * 272;
            #pragma unroll
            for (int ktp = 0; ktp < 4; ktp++) {
                uint32_t bf[4];
                ldmatrix_x4(bf, bb + ktp * 64);
                mma16816(c, afr[2 * ktp],     bf[0], bf[1]);
                mma16816(c, afr[2 * ktp + 1], bf[2], bf[3]);
            }
            swb[l4 * 100 + nt * 4 + q]       = f2h2(c[0], c[1]);
            swb[(l4 + 8) * 100 + nt * 4 + q] = f2h2(c[2], c[3]);
        }
        __syncwarp();
        #pragma unroll 2
        for (int i = lane; i < 384; i += 32) {
            int row = i / 24, wi = i % 24;
            uint4 v = *(uint4*)&swb[row * 100 + wi * 4];
            *(uint4*)&g_xall16[(row0 + mt * 16 + row) * 384 + nh * 192 + wi * 8] = v;
        }
        __syncwarp();
        __syncthreads();
        if (t < 64) g_logits[row0 + t] = lgp[t] + lgp[64 + t];
    }
}

// ================= K2: softmax over T =================
__global__ void k2_softmax()
{
    __shared__ float red[256];
    const int b = blockIdx.x, t = threadIdx.x;
    float v = (t < 200) ? g_logits[b * 200 + t] : -1e30f;
    red[t] = v; __syncthreads();
    for (int s = 128; s; s >>= 1) { if (t < s) red[t] = fmaxf(red[t], red[t + s]); __syncthreads(); }
    float mx = red[0]; __syncthreads();
    float e = (t < 200) ? __expf(v - mx) : 0.f;
    red[t] = e; __syncthreads();
    for (int s = 128; s; s >>= 1) { if (t < s) red[t] += red[t + s]; __syncthreads(); }
    float inv = __fdividef(1.f, red[0]);
    if (t < 200) g_att[b * 200 + t] = e * inv;
}

// ================= K3: GRU scan (8 rows/CTA, 128 CTAs) + fused final linear =================
// block 256 (8 warps); warp w owns h-cols [16w,16w+16) for all 3 gates.
// m16 tile: rows 0-7 real, rows 8-15 permanent zeros.
#define K3_HBUF 4352           // bytes per h buffer (16*136 halves)
#define XPAD 196               // uint32 row stride in xbuf

__global__ __launch_bounds__(256) void k3_scan(
    const float* __restrict__ targets,
    const float* __restrict__ huw, const float* __restrict__ hub,
    const float* __restrict__ hrw, const float* __restrict__ hrb,
    const float* __restrict__ hgw, const float* __restrict__ hgb,
    const float* __restrict__ lnw, const float* __restrict__ lnb,
    float* __restrict__ out)
{
    __shared__ __align__(16) __half hsm[2 * 16 * 136];
    __shared__ __align__(16) uint32_t xbuf[2][8 * XPAD];
    __shared__ float attbuf[2][8];
    __shared__ __align__(16) float xs[8][260];
    const int t = threadIdx.x, w = t >> 5, lane = t & 31;
    const int q = lane & 3, l4 = lane >> 2;
    const size_t rowb = (size_t)blockIdx.x * 8;

    // weight B-fragments: [gate][coltile j][ktile][2]
    uint32_t bfr[3][2][8][2];
    float2 bias2[3][2];
    #pragma unroll
    for (int g = 0; g < 3; g++) {
        const float* W  = (g == 0) ? huw : (g == 1) ? hrw : hgw;
        const float* Bv = (g == 0) ? hub : (g == 1) ? hrb : hgb;
        #pragma unroll
        for (int j = 0; j < 2; j++) {
            const int n = 16 * w + 8 * j + l4;
            bias2[g][j] = *(const float2*)&Bv[16 * w + 8 * j + 2 * q];
            #pragma unroll
            for (int kt = 0; kt < 8; kt++) {
                float2 wa = *(const float2*)&W[n * 128 + kt * 16 + 2 * q];
                float2 wb = *(const float2*)&W[n * 128 + kt * 16 + 2 * q + 8];
                bfr[g][j][kt][0] = f2h2(wa.x, wa.y);
                bfr[g][j][kt][1] = f2h2(wb.x, wb.y);
            }
        }
    }
    for (int i = t; i < 2 * 16 * 136; i += 256) hsm[i] = __float2half(0.f);

    // initial x/att fill for step 0 (coalesced: 8 contiguous 768B rows)
    for (int i = t; i < 1536; i += 256) {
        int row = i / 192, col = i % 192;
        xbuf[0][row * XPAD + col] =
            *(const uint32_t*)&g_xall16[((rowb + row) * 200) * 384 + col * 2];
    }
    if (t < 8) attbuf[0][t] = g_att[(rowb + t) * 200];
    __syncthreads();

    float hm[2][2] = {{0.f, 0.f}, {0.f, 0.f}};     // [j][e], row l4
    const uint32_t hb0 = smem_u32(hsm) + (lane & 15) * 272 + (lane >> 4) * 16;

    for (int step = 0; step < 200; step++) {
        const int rb = step & 1, wbuf = 1 - rb;

        // prefetch next step's x/att FIRST (max latency overlap)
        uint32_t xr6[6]; float attr = 0.f;
        if (step < 199) {
            #pragma unroll
            for (int j = 0; j < 6; j++) {
                int idx = t + j * 256;
                int row = idx / 192, col = idx % 192;
                xr6[j] = *(const uint32_t*)&g_xall16[((rowb + row) * 200 + step + 1) * 384 + col * 2];
            }
            if (t < 8) attr = g_att[(rowb + t) * 200 + step + 1];
        }

        // gather this step's x from smem (conflict-free: bank = 4*l4+q + const)
        float acc[3][2][4];
        float xg2[2][2];
        #pragma unroll
        for (int j = 0; j < 2; j++) {
            const int ci = 8 * w + 4 * j + q;
            float2 vu = __half22float2(*(__half2*)&xbuf[rb][l4 * XPAD + ci]);
            float2 vr = __half22float2(*(__half2*)&xbuf[rb][l4 * XPAD + 64 + ci]);
            float2 vg = __half22float2(*(__half2*)&xbuf[rb][l4 * XPAD + 128 + ci]);
            acc[0][j][0] = vu.x; acc[0][j][1] = vu.y; acc[0][j][2] = 0.f; acc[0][j][3] = 0.f;
            acc[1][j][0] = vr.x; acc[1][j][1] = vr.y; acc[1][j][2] = 0.f; acc[1][j][3] = 0.f;
            xg2[j][0] = vg.x; xg2[j][1] = vg.y;
            acc[2][j][0] = acc[2][j][1] = acc[2][j][2] = acc[2][j][3] = 0.f;
        }
        const float a0 = attbuf[rb][l4];

        #pragma unroll
        for (int kt = 0; kt < 8; kt++) {
            uint32_t afr[4];
            ldmatrix_x4(afr, hb0 + rb * K3_HBUF + kt * 32);
            #pragma unroll
            for (int g = 0; g < 3; g++) {
                mma16816(acc[g][0], afr, bfr[g][0][kt][0], bfr[g][0][kt][1]);
                mma16816(acc[g][1], afr, bfr[g][1][kt][0], bfr[g][1][kt][1]);
            }
        }

        float hn[2][2];
        #pragma unroll
        for (int j = 0; j < 2; j++) {
            #pragma unroll
            for (int e = 0; e < 2; e++) {
                const float bU = e ? bias2[0][j].y : bias2[0][j].x;
                const float bR = e ? bias2[1][j].y : bias2[1][j].x;
                const float bG = e ? bias2[2][j].y : bias2[2][j].x;
                float u = fmaf(tanhapx(0.5f * (acc[0][j][e] + bU)), 0.5f, 0.5f) * a0;
                float r = fmaf(tanhapx(0.5f * (acc[1][j][e] + bR)), 0.5f, 0.5f);
                float pre = xg2[j][e] + r * (acc[2][j][e] + bG);
                float gg = tanhapx(pre);
                hn[j][e] = fmaf(u, gg - hm[j][e], hm[j][e]);
            }
        }
        // publish h(t+1) (rows 0-7 only; rows 8-15 stay zero) and x(t+1)
        char* hw = (char*)hsm + wbuf * K3_HBUF;
        #pragma unroll
        for (int j = 0; j < 2; j++) {
            *(uint32_t*)(hw + l4 * 272 + (16 * w + 8 * j + 2 * q) * 2) = f2h2(hn[j][0], hn[j][1]);
            hm[j][0] = hn[j][0]; hm[j][1] = hn[j][1];
        }
        if (step < 199) {
            #pragma unroll
            for (int j = 0; j < 6; j++) {
                int idx = t + j * 256;
                int row = idx / 192, col = idx % 192;
                xbuf[wbuf][row * XPAD + col] = xr6[j];
            }
            if (t < 8) attbuf[wbuf][t] = attr;
        }
        __syncthreads();
    }

    // ---- fused final linear: out = [h, targets[:,0]] @ ln2_w^T + b ----
    #pragma unroll
    for (int j = 0; j < 2; j++) {
        xs[l4][16 * w + 8 * j + 2 * q]     = hm[j][0];
        xs[l4][16 * w + 8 * j + 2 * q + 1] = hm[j][1];
    }
    for (int i = t; i < 1024; i += 256) {
        int bb = i >> 7, c = i & 127;
        xs[bb][128 + c] = targets[(size_t)(rowb + bb) * 200 * 128 + c];
    }
    __syncthreads();
    const int col = t & 127, grp = t >> 7;
    float acc4[4];
    const float bv = lnb[col];
    #pragma unroll
    for (int i = 0; i < 4; i++) acc4[i] = bv;
    const float4* wr = (const float4*)(lnw + (size_t)col * 256);
    #pragma unroll 4
    for (int k = 0; k < 64; k++) {
        float4 wv = wr[k];
        #pragma unroll
        for (int i = 0; i < 4; i++) {
            float4 xv = *(const float4*)&xs[grp * 4 + i][k * 4];
            acc4[i] += wv.x * xv.x + wv.y * xv.y + wv.z * xv.z + wv.w * xv.w;
        }
    }
    #pragma unroll
    for (int i = 0; i < 4; i++)
        out[(rowb + grp * 4 + i) * 128 + col] = acc4[i];
}

extern "C" void kernel_launch(void* const* d_in, const int* in_sizes, int n_in,
                              void* d_out, int out_size)
{
    const float* targets = (const float*)d_in[0];
    const float* hist    = (const float*)d_in[1];
    const float* Ww  = (const float*)d_in[2];  const float* Wb  = (const float*)d_in[3];
    const float* xuw = (const float*)d_in[4];  const float* xub = (const float*)d_in[5];
    const float* huw = (const float*)d_in[6];  const float* hub = (const float*)d_in[7];
    const float* xrw = (const float*)d_in[8];  const float* xrb = (const float*)d_in[9];
    const float* hrw = (const float*)d_in[10]; const float* hrb = (const float*)d_in[11];
    const float* xgw = (const float*)d_in[12]; const float* xgb = (const float*)d_in[13];
    const float* hgw = (const float*)d_in[14]; const float* hgb = (const float*)d_in[15];
    const float* lnw = (const float*)d_in[16]; const float* lnb = (const float*)d_in[17];
    float* out = (float*)d_out;

    cudaFuncSetAttribute(k1_ff, cudaFuncAttributeMaxDynamicSharedMemorySize, K1_SMEM);

    k1_ff<<<400, 256, K1_SMEM>>>(targets, hist, Ww, Wb, xuw, xub, xrw, xrb, xgw, xgb);
    k2_softmax<<<1024, 256>>>();
    k3_scan<<<128, 256>>>(targets, huw, hub, hrw, hrb, hgw, hgb, lnw, lnb, out);
}

// round 10
// speedup vs baseline: 8.3748x; 1.4741x over previous
#include <cuda_runtime.h>
#include <cuda_fp16.h>
#include <cstdint>

// B=1024, T=200, IN=H=128. rows = 204800.
__device__ __half g_xall16[(size_t)204800 * 384];   // [flat row][xu|xr|xg] fp16, biases folded
__device__ float g_logits[204800];
__device__ float g_att[204800];

__device__ __forceinline__ uint32_t smem_u32(const void* p) {
    return (uint32_t)__cvta_generic_to_shared(p);
}
__device__ __forceinline__ void ldmatrix_x4(uint32_t a[4], uint32_t addr) {
    asm volatile("ldmatrix.sync.aligned.m8n8.x4.shared.b16 {%0,%1,%2,%3}, [%4];"
                 : "=r"(a[0]), "=r"(a[1]), "=r"(a[2]), "=r"(a[3]) : "r"(addr));
}
__device__ __forceinline__ void mma16816(float c[4], const uint32_t a[4], uint32_t b0, uint32_t b1) {
    asm volatile("mma.sync.aligned.m16n8k16.row.col.f32.f16.f16.f32 "
                 "{%0,%1,%2,%3},{%4,%5,%6,%7},{%8,%9},{%0,%1,%2,%3};"
                 : "+f"(c[0]), "+f"(c[1]), "+f"(c[2]), "+f"(c[3])
                 : "r"(a[0]), "r"(a[1]), "r"(a[2]), "r"(a[3]), "r"(b0), "r"(b1));
}
__device__ __forceinline__ uint32_t f2h2(float x, float y) {
    __half2 h = __floats2half2_rn(x, y);
    return *reinterpret_cast<uint32_t*>(&h);
}
__device__ __forceinline__ float tanhapx(float x) {
    float y; asm("tanh.approx.f32 %0, %1;" : "=f"(y) : "f"(x)); return y;
}

// ================= K1: logits + x projections, register-resident weights =================
// grid 148 persistent, block 512 (16 warps). Warp w owns 32 cols of [Ww|xu|xr|xg].
// Tiles of 64 rows; per tile: coop load inputs fp16 -> smem, A-frags via ldmatrix,
// mma against register B-frags. Logit warps fuse hist-dot; x warps stage+flush coalesced.
// dynamic smem: tg16 17408 | hs16 17408 | swb 15360 | lgp 1024 = 51200 B
#define K1_HS_OFF  17408
#define K1_SWB_OFF 34816
#define K1_LGP_OFF 50176
#define K1_SMEM    51200
#define K1_TILES   3200

__global__ __launch_bounds__(512) void k1_ff(
    const float* __restrict__ targets, const float* __restrict__ hist,
    const float* __restrict__ Ww,  const float* __restrict__ Wb,
    const float* __restrict__ xuw, const float* __restrict__ xub,
    const float* __restrict__ xrw, const float* __restrict__ xrb,
    const float* __restrict__ xgw, const float* __restrict__ xgb)
{
    extern __shared__ char sm[];
    __half* tg16 = (__half*)sm;
    __half* hs16 = (__half*)(sm + K1_HS_OFF);
    uint32_t* swb = (uint32_t*)(sm + K1_SWB_OFF);
    float* lgp = (float*)(sm + K1_LGP_OFF);

    const int t = threadIdx.x, w = t >> 5, lane = t & 31;
    const int q = lane & 3, l4 = lane >> 2;
    const int g = w >> 2;                 // 0: logits(Ww), 1: xu, 2: xr, 3: xg
    const int cb = 32 * (w & 3);          // column base within the 128-wide gate
    const bool is_logit = (g == 0);

    const float* W  = (g == 0) ? Ww  : (g == 1) ? xuw : (g == 2) ? xrw : xgw;
    const float* Bv = (g == 0) ? Wb  : (g == 1) ? xub : (g == 2) ? xrb : xgb;

    // ---- load warp's weight B-fragments into registers (once) ----
    uint32_t bfr[4][8][2];
    float2 bs[4];
    #pragma unroll
    for (int ct = 0; ct < 4; ct++) {
        const int n = cb + 8 * ct + l4;
        bs[ct] = *(const float2*)&Bv[cb + 8 * ct + 2 * q];
        #pragma unroll
        for (int kt = 0; kt < 8; kt++) {
            float2 wa = *(const float2*)&W[n * 128 + kt * 16 + 2 * q];
            float2 wb = *(const float2*)&W[n * 128 + kt * 16 + 2 * q + 8];
            bfr[ct][kt][0] = f2h2(wa.x, wa.y);
            bfr[ct][kt][1] = f2h2(wb.x, wb.y);
        }
    }

    const uint32_t abase = smem_u32(is_logit ? tg16 : hs16)
                         + (lane & 15) * 272 + (lane >> 4) * 16;
    uint32_t* swbw = swb + (w - 4) * 320;          // x warps only (w>=4)
    const int gc0 = (g - 1) * 128 + cb;            // x warps: col base in g_xall16 row

    for (int tile = blockIdx.x; tile < K1_TILES; tile += 148) {
        const size_t row0 = (size_t)tile * 64;
        __syncthreads();   // previous tile's smem fully consumed
        #pragma unroll
        for (int j = 0; j < 8; j++) {
            int idx = t + 512 * j;                 // 4096 half2 slots per array
            int r = idx >> 6, c2 = idx & 63;
            float2 tv = *(const float2*)&targets[(row0 + r) * 128 + 2 * c2];
            float2 hv = *(const float2*)&hist[(row0 + r) * 128 + 2 * c2];
            *(__half2*)&tg16[r * 136 + 2 * c2] = __floats2half2_rn(tv.x, tv.y);
            *(__half2*)&hs16[r * 136 + 2 * c2] = __floats2half2_rn(hv.x, hv.y);
        }
        __syncthreads();

        #pragma unroll
        for (int mt = 0; mt < 4; mt++) {
            float acc[4][4];
            #pragma unroll
            for (int ct = 0; ct < 4; ct++) {
                if (is_logit) {
                    acc[ct][0] = acc[ct][1] = acc[ct][2] = acc[ct][3] = 0.f;
                } else {
                    acc[ct][0] = bs[ct].x; acc[ct][1] = bs[ct].y;
                    acc[ct][2] = bs[ct].x; acc[ct][3] = bs[ct].y;
                }
            }
            const uint32_t ab = abase + mt * 4352;
            #pragma unroll
            for (int kc = 0; kc < 2; kc++) {       // k chunks of 4 to cap registers
                uint32_t af[4][4];
                #pragma unroll
                for (int k4 = 0; k4 < 4; k4++)
                    ldmatrix_x4(af[k4], ab + (4 * kc + k4) * 32);
                #pragma unroll
                for (int ct = 0; ct < 4; ct++)
                    #pragma unroll
                    for (int k4 = 0; k4 < 4; k4++)
                        mma16816(acc[ct], af[k4], bfr[ct][4 * kc + k4][0], bfr[ct][4 * kc + k4][1]);
            }
            const int r0 = mt * 16 + l4, r1 = r0 + 8;
            if (is_logit) {
                float p0 = 0.f, p1 = 0.f;
                #pragma unroll
                for (int ct = 0; ct < 4; ct++) {
                    const int col = cb + 8 * ct + 2 * q;
                    float2 h0 = __half22float2(*(const __half2*)&hs16[r0 * 136 + col]);
                    float2 h1 = __half22float2(*(const __half2*)&hs16[r1 * 136 + col]);
                    p0 += (acc[ct][0] + bs[ct].x) * h0.x + (acc[ct][1] + bs[ct].y) * h0.y;
                    p1 += (acc[ct][2] + bs[ct].x) * h1.x + (acc[ct][3] + bs[ct].y) * h1.y;
                }
                p0 += __shfl_xor_sync(~0u, p0, 1); p0 += __shfl_xor_sync(~0u, p0, 2);
                p1 += __shfl_xor_sync(~0u, p1, 1); p1 += __shfl_xor_sync(~0u, p1, 2);
                if (q == 0) {
                    lgp[w * 64 + r0] = p0;
                    lgp[w * 64 + r1] = p1;
                }
            } else {
                // stage in swb (stride 20 -> conflict-free STS), then coalesced flush
                #pragma unroll
                for (int ct = 0; ct < 4; ct++) {
                    swbw[l4 * 20 + ct * 4 + q]       = f2h2(acc[ct][0], acc[ct][1]);
                    swbw[(l4 + 8) * 20 + ct * 4 + q] = f2h2(acc[ct][2], acc[ct][3]);
                }
                __syncwarp();
                #pragma unroll
                for (int i = lane; i < 256; i += 32) {
                    int row = i >> 4, c = i & 15;
                    uint32_t v = swbw[row * 20 + c];
                    *(uint32_t*)&g_xall16[(row0 + mt * 16 + row) * 384 + gc0 + 2 * c] = v;
                }
                __syncwarp();
            }
        }
        __syncthreads();
        if (t < 64)
            g_logits[row0 + t] = lgp[t] + lgp[64 + t] + lgp[128 + t] + lgp[192 + t];
    }
}

// ================= K2: softmax over T =================
__global__ void k2_softmax()
{
    __shared__ float red[256];
    const int b = blockIdx.x, t = threadIdx.x;
    float v = (t < 200) ? g_logits[b * 200 + t] : -1e30f;
    red[t] = v; __syncthreads();
    for (int s = 128; s; s >>= 1) { if (t < s) red[t] = fmaxf(red[t], red[t + s]); __syncthreads(); }
    float mx = red[0]; __syncthreads();
    float e = (t < 200) ? __expf(v - mx) : 0.f;
    red[t] = e; __syncthreads();
    for (int s = 128; s; s >>= 1) { if (t < s) red[t] += red[t + s]; __syncthreads(); }
    float inv = __fdividef(1.f, red[0]);
    if (t < 200) g_att[b * 200 + t] = e * inv;
}

// ================= K3: GRU scan (8 rows/CTA, 128 CTAs) + fused final linear =================
#define K3_HBUF 4352
#define XPAD 196

__global__ __launch_bounds__(256) void k3_scan(
    const float* __restrict__ targets,
    const float* __restrict__ huw, const float* __restrict__ hub,
    const float* __restrict__ hrw, const float* __restrict__ hrb,
    const float* __restrict__ hgw, const float* __restrict__ hgb,
    const float* __restrict__ lnw, const float* __restrict__ lnb,
    float* __restrict__ out)
{
    __shared__ __align__(16) __half hsm[2 * 16 * 136];
    __shared__ __align__(16) uint32_t xbuf[2][8 * XPAD];
    __shared__ float attbuf[2][8];
    __shared__ __align__(16) float xs[8][260];
    const int t = threadIdx.x, w = t >> 5, lane = t & 31;
    const int q = lane & 3, l4 = lane >> 2;
    const size_t rowb = (size_t)blockIdx.x * 8;

    uint32_t bfr[3][2][8][2];
    float2 bias2[3][2];
    #pragma unroll
    for (int g = 0; g < 3; g++) {
        const float* W  = (g == 0) ? huw : (g == 1) ? hrw : hgw;
        const float* Bv = (g == 0) ? hub : (g == 1) ? hrb : hgb;
        #pragma unroll
        for (int j = 0; j < 2; j++) {
            const int n = 16 * w + 8 * j + l4;
            bias2[g][j] = *(const float2*)&Bv[16 * w + 8 * j + 2 * q];
            #pragma unroll
            for (int kt = 0; kt < 8; kt++) {
                float2 wa = *(const float2*)&W[n * 128 + kt * 16 + 2 * q];
                float2 wb = *(const float2*)&W[n * 128 + kt * 16 + 2 * q + 8];
                bfr[g][j][kt][0] = f2h2(wa.x, wa.y);
                bfr[g][j][kt][1] = f2h2(wb.x, wb.y);
            }
        }
    }
    for (int i = t; i < 2 * 16 * 136; i += 256) hsm[i] = __float2half(0.f);

    for (int i = t; i < 1536; i += 256) {
        int row = i / 192, col = i % 192;
        xbuf[0][row * XPAD + col] =
            *(const uint32_t*)&g_xall16[((rowb + row) * 200) * 384 + col * 2];
    }
    if (t < 8) attbuf[0][t] = g_att[(rowb + t) * 200];
    __syncthreads();

    float hm[2][2] = {{0.f, 0.f}, {0.f, 0.f}};
    const uint32_t hb0 = smem_u32(hsm) + (lane & 15) * 272 + (lane >> 4) * 16;

    for (int step = 0; step < 200; step++) {
        const int rb = step & 1, wbuf = 1 - rb;

        uint32_t xr6[6]; float attr = 0.f;
        if (step < 199) {
            #pragma unroll
            for (int j = 0; j < 6; j++) {
                int idx = t + j * 256;
                int row = idx / 192, col = idx % 192;
                xr6[j] = *(const uint32_t*)&g_xall16[((rowb + row) * 200 + step + 1) * 384 + col * 2];
            }
            if (t < 8) attr = g_att[(rowb + t) * 200 + step + 1];
        }

        float acc[3][2][4];
        float xg2[2][2];
        #pragma unroll
        for (int j = 0; j < 2; j++) {
            const int ci = 8 * w + 4 * j + q;
            float2 vu = __half22float2(*(__half2*)&xbuf[rb][l4 * XPAD + ci]);
            float2 vr = __half22float2(*(__half2*)&xbuf[rb][l4 * XPAD + 64 + ci]);
            float2 vg = __half22float2(*(__half2*)&xbuf[rb][l4 * XPAD + 128 + ci]);
            acc[0][j][0] = vu.x; acc[0][j][1] = vu.y; acc[0][j][2] = 0.f; acc[0][j][3] = 0.f;
            acc[1][j][0] = vr.x; acc[1][j][1] = vr.y; acc[1][j][2] = 0.f; acc[1][j][3] = 0.f;
            xg2[j][0] = vg.x; xg2[j][1] = vg.y;
            acc[2][j][0] = acc[2][j][1] = acc[2][j][2] = acc[2][j][3] = 0.f;
        }
        const float a0 = attbuf[rb][l4];

        #pragma unroll
        for (int kt = 0; kt < 8; kt++) {
            uint32_t afr[4];
            ldmatrix_x4(afr, hb0 + rb * K3_HBUF + kt * 32);
            #pragma unroll
            for (int g = 0; g < 3; g++) {
                mma16816(acc[g][0], afr, bfr[g][0][kt][0], bfr[g][0][kt][1]);
                mma16816(acc[g][1], afr, bfr[g][1][kt][0], bfr[g][1][kt][1]);
            }
        }

        float hn[2][2];
        #pragma unroll
        for (int j = 0; j < 2; j++) {
            #pragma unroll
            for (int e = 0; e < 2; e++) {
                const float bU = e ? bias2[0][j].y : bias2[0][j].x;
                const float bR = e ? bias2[1][j].y : bias2[1][j].x;
                const float bG = e ? bias2[2][j].y : bias2[2][j].x;
                float u = fmaf(tanhapx(0.5f * (acc[0][j][e] + bU)), 0.5f, 0.5f) * a0;
                float r = fmaf(tanhapx(0.5f * (acc[1][j][e] + bR)), 0.5f, 0.5f);
                float pre = xg2[j][e] + r * (acc[2][j][e] + bG);
                float gg = tanhapx(pre);
                hn[j][e] = fmaf(u, gg - hm[j][e], hm[j][e]);
            }
        }
        char* hw = (char*)hsm + wbuf * K3_HBUF;
        #pragma unroll
        for (int j = 0; j < 2; j++) {
            *(uint32_t*)(hw + l4 * 272 + (16 * w + 8 * j + 2 * q) * 2) = f2h2(hn[j][0], hn[j][1]);
            hm[j][0] = hn[j][0]; hm[j][1] = hn[j][1];
        }
        if (step < 199) {
            #pragma unroll
            for (int j = 0; j < 6; j++) {
                int idx = t + j * 256;
                int row = idx / 192, col = idx % 192;
                xbuf[wbuf][row * XPAD + col] = xr6[j];
            }
            if (t < 8) attbuf[wbuf][t] = attr;
        }
        __syncthreads();
    }

    // ---- fused final linear: out = [h, targets[:,0]] @ ln2_w^T + b ----
    #pragma unroll
    for (int j = 0; j < 2; j++) {
        xs[l4][16 * w + 8 * j + 2 * q]     = hm[j][0];
        xs[l4][16 * w + 8 * j + 2 * q + 1] = hm[j][1];
    }
    for (int i = t; i < 1024; i += 256) {
        int bb = i >> 7, c = i & 127;
        xs[bb][128 + c] = targets[(size_t)(rowb + bb) * 200 * 128 + c];
    }
    __syncthreads();
    const int col = t & 127, grp = t >> 7;
    float acc4[4];
    const float bv = lnb[col];
    #pragma unroll
    for (int i = 0; i < 4; i++) acc4[i] = bv;
    const float4* wr = (const float4*)(lnw + (size_t)col * 256);
    #pragma unroll 4
    for (int k = 0; k < 64; k++) {
        float4 wv = wr[k];
        #pragma unroll
        for (int i = 0; i < 4; i++) {
            float4 xv = *(const float4*)&xs[grp * 4 + i][k * 4];
            acc4[i] += wv.x * xv.x + wv.y * xv.y + wv.z * xv.z + wv.w * xv.w;
        }
    }
    #pragma unroll
    for (int i = 0; i < 4; i++)
        out[(rowb + grp * 4 + i) * 128 + col] = acc4[i];
}

extern "C" void kernel_launch(void* const* d_in, const int* in_sizes, int n_in,
                              void* d_out, int out_size)
{
    const float* targets = (const float*)d_in[0];
    const float* hist    = (const float*)d_in[1];
    const float* Ww  = (const float*)d_in[2];  const float* Wb  = (const float*)d_in[3];
    const float* xuw = (const float*)d_in[4];  const float* xub = (const float*)d_in[5];
    const float* huw = (const float*)d_in[6];  const float* hub = (const float*)d_in[7];
    const float* xrw = (const float*)d_in[8];  const float* xrb = (const float*)d_in[9];
    const float* hrw = (const float*)d_in[10]; const float* hrb = (const float*)d_in[11];
    const float* xgw = (const float*)d_in[12]; const float* xgb = (const float*)d_in[13];
    const float* hgw = (const float*)d_in[14]; const float* hgb = (const float*)d_in[15];
    const float* lnw = (const float*)d_in[16]; const float* lnb = (const float*)d_in[17];
    float* out = (float*)d_out;

    cudaFuncSetAttribute(k1_ff, cudaFuncAttributeMaxDynamicSharedMemorySize, K1_SMEM);

    k1_ff<<<148, 512, K1_SMEM>>>(targets, hist, Ww, Wb, xuw, xub, xrw, xrb, xgw, xgb);
    k2_softmax<<<1024, 256>>>();
    k3_scan<<<128, 256>>>(targets, huw, hub, hrw, hrb, hgw, hgb, lnw, lnb, out);
}